// round 2
// baseline (speedup 1.0000x reference)
#include <cuda_runtime.h>
#include <cuda_bf16.h>

// Problem constants
#define BB 2
#define TT 2048
#define DMODEL 1024
#define NHEAD 16
#define HDIM 64

// Scratch (device globals: allocation-free rule)
__device__ float g_Q[(size_t)BB * TT * DMODEL];
__device__ float g_K[(size_t)BB * TT * DMODEL];
__device__ float g_V[(size_t)BB * TT * DMODEL];
__device__ float g_AO[(size_t)BB * TT * DMODEL];

// ---------------------------------------------------------------------------
// SGEMM (NT): C[M,N] = A[M,K] * W[N,K]^T, M=4096, N=1024, K=1024
// 128x128 tile, BK=8, 256 threads, 8x8 register tile per thread.
// ---------------------------------------------------------------------------
__device__ __forceinline__ void sgemm_nt_body(const float* __restrict__ A,
                                              const float* __restrict__ W,
                                              float* __restrict__ C) {
    __shared__ float As[8][128];
    __shared__ float Bs[8][128];

    const int tid = threadIdx.x;
    const int m0 = blockIdx.y * 128;
    const int n0 = blockIdx.x * 128;

    const int lr = tid >> 1;          // 0..127 row within tile
    const int lc = (tid & 1) * 4;     // 0 or 4 (k offset)

    const int ty = tid >> 4;          // 0..15
    const int tx = tid & 15;          // 0..15

    float acc[8][8];
#pragma unroll
    for (int i = 0; i < 8; i++)
#pragma unroll
        for (int j = 0; j < 8; j++) acc[i][j] = 0.f;

    const float* Ap = A + (size_t)(m0 + lr) * DMODEL + lc;
    const float* Wp = W + (size_t)(n0 + lr) * DMODEL + lc;

    for (int k0 = 0; k0 < DMODEL; k0 += 8) {
        float4 av = *(const float4*)(Ap + k0);
        float4 bv = *(const float4*)(Wp + k0);
        __syncthreads();
        As[lc + 0][lr] = av.x; As[lc + 1][lr] = av.y;
        As[lc + 2][lr] = av.z; As[lc + 3][lr] = av.w;
        Bs[lc + 0][lr] = bv.x; Bs[lc + 1][lr] = bv.y;
        Bs[lc + 2][lr] = bv.z; Bs[lc + 3][lr] = bv.w;
        __syncthreads();
#pragma unroll
        for (int kk = 0; kk < 8; kk++) {
            float ar[8], br[8];
            *(float4*)(ar)     = *(const float4*)(&As[kk][ty * 8]);
            *(float4*)(ar + 4) = *(const float4*)(&As[kk][ty * 8 + 4]);
            *(float4*)(br)     = *(const float4*)(&Bs[kk][tx * 8]);
            *(float4*)(br + 4) = *(const float4*)(&Bs[kk][tx * 8 + 4]);
#pragma unroll
            for (int i = 0; i < 8; i++)
#pragma unroll
                for (int j = 0; j < 8; j++) acc[i][j] += ar[i] * br[j];
        }
    }

#pragma unroll
    for (int i = 0; i < 8; i++) {
        float* Cp = C + (size_t)(m0 + ty * 8 + i) * DMODEL + n0 + tx * 8;
        float4 v0 = make_float4(acc[i][0], acc[i][1], acc[i][2], acc[i][3]);
        float4 v1 = make_float4(acc[i][4], acc[i][5], acc[i][6], acc[i][7]);
        *(float4*)(Cp)     = v0;
        *(float4*)(Cp + 4) = v1;
    }
}

__global__ __launch_bounds__(256) void qkv_kernel(const float* __restrict__ x,
                                                  const float* __restrict__ Wq,
                                                  const float* __restrict__ Wk,
                                                  const float* __restrict__ Wv) {
    const float* W;
    float* C;
    if (blockIdx.z == 0)      { W = Wq; C = g_Q; }
    else if (blockIdx.z == 1) { W = Wk; C = g_K; }
    else                      { W = Wv; C = g_V; }
    sgemm_nt_body(x, W, C);
}

__global__ __launch_bounds__(256) void oproj_kernel(const float* __restrict__ Wo,
                                                    float* __restrict__ out) {
    sgemm_nt_body(g_AO, Wo, out);
}

// ---------------------------------------------------------------------------
// Flash attention (causal), fp32.
// Grid: (T/128, NHEAD, BB), 128 threads. Thread t owns query row qt + t.
// ---------------------------------------------------------------------------
#define QS_LD 68   // padded row length for Q tile (float4-aligned)
#define FLASH_SMEM ((128 * QS_LD + 2 * 64 * 64) * sizeof(float))

__global__ __launch_bounds__(128) void flash_kernel() {
    extern __shared__ float sm[];
    float* Qs = sm;                   // 128 x QS_LD
    float* Ks = sm + 128 * QS_LD;     // 64 x 64
    float* Vs = Ks + 64 * 64;         // 64 x 64

    const int t = threadIdx.x;
    const int h = blockIdx.y;
    const int b = blockIdx.z;
    const int qt = blockIdx.x * 128;
    const int q = qt + t;

    const float scale = 0.125f;  // 1/sqrt(64)

    const float* Qg = g_Q + ((size_t)(b * TT + qt)) * DMODEL + h * HDIM;
#pragma unroll
    for (int i = 0; i < 16; i++) {
        int idx = i * 128 + t;
        int r = idx >> 4;
        int c4 = (idx & 15) * 4;
        float4 v = *(const float4*)(Qg + (size_t)r * DMODEL + c4);
        v.x *= scale; v.y *= scale; v.z *= scale; v.w *= scale;
        *(float4*)(Qs + r * QS_LD + c4) = v;
    }

    float4 O4[16];
#pragma unroll
    for (int i = 0; i < 16; i++) O4[i] = make_float4(0.f, 0.f, 0.f, 0.f);
    float mrow = -1e30f;
    float lrow = 0.f;

    const float* Kg0 = g_K + ((size_t)b * TT) * DMODEL + h * HDIM;
    const float* Vg0 = g_V + ((size_t)b * TT) * DMODEL + h * HDIM;

    const int nkt = qt / 64 + 2;  // causal: key tiles needed

    for (int kt = 0; kt < nkt; kt++) {
        const int k0 = kt * 64;

        __syncthreads();
#pragma unroll
        for (int i = 0; i < 8; i++) {
            int idx = i * 128 + t;
            int r = idx >> 4;
            int c4 = (idx & 15) * 4;
            *(float4*)(Ks + r * 64 + c4) = *(const float4*)(Kg0 + (size_t)(k0 + r) * DMODEL + c4);
            *(float4*)(Vs + r * 64 + c4) = *(const float4*)(Vg0 + (size_t)(k0 + r) * DMODEL + c4);
        }
        __syncthreads();

        float s[64];
#pragma unroll
        for (int j = 0; j < 64; j++) s[j] = 0.f;
#pragma unroll 1
        for (int d4 = 0; d4 < 64; d4 += 4) {
            float4 qv = *(const float4*)(Qs + t * QS_LD + d4);
#pragma unroll
            for (int j = 0; j < 64; j++) {
                float4 kv = *(const float4*)(Ks + j * 64 + d4);
                s[j] += qv.x * kv.x + qv.y * kv.y + qv.z * kv.z + qv.w * kv.w;
            }
        }

        if (k0 + 63 > qt) {
#pragma unroll
            for (int j = 0; j < 64; j++)
                if (k0 + j > q) s[j] = -1e30f;
        }

        float mt = -1e30f;
#pragma unroll
        for (int j = 0; j < 64; j++) mt = fmaxf(mt, s[j]);
        float mnew = fmaxf(mrow, mt);
        float alpha = __expf(mrow - mnew);
        mrow = mnew;
        lrow *= alpha;
#pragma unroll
        for (int i = 0; i < 16; i++) {
            O4[i].x *= alpha; O4[i].y *= alpha;
            O4[i].z *= alpha; O4[i].w *= alpha;
        }

        float pl[64];  // const-index writes, dynamic reads -> local memory
        float lsum = 0.f;
#pragma unroll
        for (int j = 0; j < 64; j++) {
            float p = __expf(s[j] - mnew);
            pl[j] = p;
            lsum += p;
        }
        lrow += lsum;

#pragma unroll 1
        for (int j = 0; j < 64; j++) {
            float p = pl[j];
            const float* vrow = Vs + j * 64;
#pragma unroll
            for (int i = 0; i < 16; i++) {
                float4 v = *(const float4*)(vrow + i * 4);
                O4[i].x += p * v.x; O4[i].y += p * v.y;
                O4[i].z += p * v.z; O4[i].w += p * v.w;
            }
        }
    }

    const float inv = 1.f / lrow;
    float* AOg = g_AO + ((size_t)(b * TT + q)) * DMODEL + h * HDIM;
#pragma unroll
    for (int i = 0; i < 16; i++) {
        float4 o = O4[i];
        o.x *= inv; o.y *= inv; o.z *= inv; o.w *= inv;
        *(float4*)(AOg + i * 4) = o;
    }
}

// ---------------------------------------------------------------------------
// Launch
// ---------------------------------------------------------------------------
extern "C" void kernel_launch(void* const* d_in, const int* in_sizes, int n_in,
                              void* d_out, int out_size) {
    const float* x  = (const float*)d_in[0];
    const float* Wq = (const float*)d_in[1];
    const float* Wk = (const float*)d_in[2];
    const float* Wv = (const float*)d_in[3];
    const float* Wo = (const float*)d_in[4];
    float* out = (float*)d_out;

    cudaFuncSetAttribute(flash_kernel, cudaFuncAttributeMaxDynamicSharedMemorySize,
                         (int)FLASH_SMEM);

    dim3 gqkv(DMODEL / 128, (BB * TT) / 128, 3);
    qkv_kernel<<<gqkv, 256>>>(x, Wq, Wk, Wv);

    dim3 gatt(TT / 128, NHEAD, BB);
    flash_kernel<<<gatt, 128, FLASH_SMEM>>>();

    dim3 gout(DMODEL / 128, (BB * TT) / 128, 1);
    oproj_kernel<<<gout, 256>>>(Wo, out);
}

// round 4
// speedup vs baseline: 1.3321x; 1.3321x over previous
#include <cuda_runtime.h>
#include <cuda_bf16.h>
#include <cstdint>

// Problem constants
#define BB 2
#define TT 2048
#define DMODEL 1024
#define NHEAD 16
#define HDIM 64

// Scratch (device globals: allocation-free rule)
__device__ float g_Q[(size_t)BB * TT * DMODEL];
__device__ float g_K[(size_t)BB * TT * DMODEL];
__device__ float g_V[(size_t)BB * TT * DMODEL];
__device__ float g_AO[(size_t)BB * TT * DMODEL];

// ---------------------------------------------------------------------------
// Helpers
// ---------------------------------------------------------------------------
__device__ __forceinline__ uint32_t f2tf32(float f) {
    uint32_t u;
    asm("cvt.rna.tf32.f32 %0, %1;" : "=r"(u) : "f"(f));
    return u;
}

#define MMA_TF32(c, a, b)                                                     \
    asm volatile(                                                             \
        "mma.sync.aligned.m16n8k8.row.col.f32.tf32.tf32.f32 "                 \
        "{%0,%1,%2,%3}, {%4,%5,%6,%7}, {%8,%9}, {%0,%1,%2,%3};"               \
        : "+f"((c)[0]), "+f"((c)[1]), "+f"((c)[2]), "+f"((c)[3])              \
        : "r"((a)[0]), "r"((a)[1]), "r"((a)[2]), "r"((a)[3]),                 \
          "r"((b)[0]), "r"((b)[1]))

// ---------------------------------------------------------------------------
// TF32 mma.sync GEMM (NT): C[M,N] = A[M,K] * W[N,K]^T
// CTA 128x128, 256 threads (8 warps as 2m x 4n), warp tile 64x32, BK=32.
// Smem tiles [row][k] padded to 36 words/row (conflict-free frag gather).
// ---------------------------------------------------------------------------
#define SLD 36  // padded row length (words)

__device__ __forceinline__ void gemm128_mma(const float* __restrict__ A,
                                            const float* __restrict__ W,
                                            float* __restrict__ C) {
    __shared__ uint32_t sA[128 * SLD];
    __shared__ uint32_t sB[128 * SLD];

    const int tid = threadIdx.x;
    const int wid = tid >> 5;
    const int lane = tid & 31;
    const int gid = lane >> 2;   // group id 0..7
    const int tig = lane & 3;    // thread in group 0..3

    const int wm = wid >> 2;     // 0..1 : warp m (64 rows each)
    const int wn = wid & 3;      // 0..3 : warp n (32 cols each)

    const int m0 = blockIdx.y * 128;
    const int n0 = blockIdx.x * 128;

    float acc[4][4][4];
#pragma unroll
    for (int mt = 0; mt < 4; mt++)
#pragma unroll
        for (int nt = 0; nt < 4; nt++)
#pragma unroll
            for (int r = 0; r < 4; r++) acc[mt][nt][r] = 0.f;

    const float* Ap = A + (size_t)m0 * DMODEL;
    const float* Wp = W + (size_t)n0 * DMODEL;

    // staging indices: 1024 float4 loads per tile, 4 per thread
    const int sr = tid >> 1;            // not used directly; see loop

    for (int k0 = 0; k0 < DMODEL; k0 += 32) {
        __syncthreads();
#pragma unroll
        for (int i = 0; i < 4; i++) {
            int idx = i * 256 + tid;
            int r = idx >> 3;           // 0..127
            int c4 = (idx & 7) * 4;     // 0,4,...,28
            float4 av = *(const float4*)(Ap + (size_t)r * DMODEL + k0 + c4);
            float4 wv = *(const float4*)(Wp + (size_t)r * DMODEL + k0 + c4);
            uint4 at = make_uint4(f2tf32(av.x), f2tf32(av.y), f2tf32(av.z), f2tf32(av.w));
            uint4 wt = make_uint4(f2tf32(wv.x), f2tf32(wv.y), f2tf32(wv.z), f2tf32(wv.w));
            *(uint4*)(&sA[r * SLD + c4]) = at;
            *(uint4*)(&sB[r * SLD + c4]) = wt;
        }
        __syncthreads();

#pragma unroll
        for (int ks = 0; ks < 4; ks++) {
            const int kk = ks * 8;
            uint32_t af[4][4];
#pragma unroll
            for (int mt = 0; mt < 4; mt++) {
                int m = wm * 64 + mt * 16;
                af[mt][0] = sA[(m + gid) * SLD + kk + tig];
                af[mt][1] = sA[(m + 8 + gid) * SLD + kk + tig];
                af[mt][2] = sA[(m + gid) * SLD + kk + 4 + tig];
                af[mt][3] = sA[(m + 8 + gid) * SLD + kk + 4 + tig];
            }
            uint32_t bf[4][2];
#pragma unroll
            for (int nt = 0; nt < 4; nt++) {
                int n = wn * 32 + nt * 8;
                bf[nt][0] = sB[(n + gid) * SLD + kk + tig];
                bf[nt][1] = sB[(n + gid) * SLD + kk + 4 + tig];
            }
#pragma unroll
            for (int mt = 0; mt < 4; mt++)
#pragma unroll
                for (int nt = 0; nt < 4; nt++)
                    MMA_TF32(acc[mt][nt], af[mt], bf[nt]);
        }
    }

    // Epilogue: c0/c1 at (row=gid, col=2*tig), c2/c3 at (row=gid+8, col=2*tig)
#pragma unroll
    for (int mt = 0; mt < 4; mt++) {
        int mbase = m0 + wm * 64 + mt * 16;
#pragma unroll
        for (int nt = 0; nt < 4; nt++) {
            int nbase = n0 + wn * 32 + nt * 8 + 2 * tig;
            float* C0 = C + (size_t)(mbase + gid) * DMODEL + nbase;
            float* C1 = C + (size_t)(mbase + 8 + gid) * DMODEL + nbase;
            *(float2*)C0 = make_float2(acc[mt][nt][0], acc[mt][nt][1]);
            *(float2*)C1 = make_float2(acc[mt][nt][2], acc[mt][nt][3]);
        }
    }
}

__global__ __launch_bounds__(256) void qkv_kernel(const float* __restrict__ x,
                                                  const float* __restrict__ Wq,
                                                  const float* __restrict__ Wk,
                                                  const float* __restrict__ Wv) {
    const float* W;
    float* C;
    if (blockIdx.z == 0)      { W = Wq; C = g_Q; }
    else if (blockIdx.z == 1) { W = Wk; C = g_K; }
    else                      { W = Wv; C = g_V; }
    gemm128_mma(x, W, C);
}

__global__ __launch_bounds__(256) void oproj_kernel(const float* __restrict__ Wo,
                                                    float* __restrict__ out) {
    gemm128_mma(g_AO, Wo, out);
}

// ---------------------------------------------------------------------------
// Flash attention (causal), fp32 — UNCHANGED from R1.
// ---------------------------------------------------------------------------
#define QS_LD 68
#define FLASH_SMEM ((128 * QS_LD + 2 * 64 * 64) * sizeof(float))

__global__ __launch_bounds__(128) void flash_kernel() {
    extern __shared__ float sm[];
    float* Qs = sm;
    float* Ks = sm + 128 * QS_LD;
    float* Vs = Ks + 64 * 64;

    const int t = threadIdx.x;
    const int h = blockIdx.y;
    const int b = blockIdx.z;
    const int qt = blockIdx.x * 128;
    const int q = qt + t;

    const float scale = 0.125f;

    const float* Qg = g_Q + ((size_t)(b * TT + qt)) * DMODEL + h * HDIM;
#pragma unroll
    for (int i = 0; i < 16; i++) {
        int idx = i * 128 + t;
        int r = idx >> 4;
        int c4 = (idx & 15) * 4;
        float4 v = *(const float4*)(Qg + (size_t)r * DMODEL + c4);
        v.x *= scale; v.y *= scale; v.z *= scale; v.w *= scale;
        *(float4*)(Qs + r * QS_LD + c4) = v;
    }

    float4 O4[16];
#pragma unroll
    for (int i = 0; i < 16; i++) O4[i] = make_float4(0.f, 0.f, 0.f, 0.f);
    float mrow = -1e30f;
    float lrow = 0.f;

    const float* Kg0 = g_K + ((size_t)b * TT) * DMODEL + h * HDIM;
    const float* Vg0 = g_V + ((size_t)b * TT) * DMODEL + h * HDIM;

    const int nkt = qt / 64 + 2;

    for (int kt = 0; kt < nkt; kt++) {
        const int k0 = kt * 64;

        __syncthreads();
#pragma unroll
        for (int i = 0; i < 8; i++) {
            int idx = i * 128 + t;
            int r = idx >> 4;
            int c4 = (idx & 15) * 4;
            *(float4*)(Ks + r * 64 + c4) = *(const float4*)(Kg0 + (size_t)(k0 + r) * DMODEL + c4);
            *(float4*)(Vs + r * 64 + c4) = *(const float4*)(Vg0 + (size_t)(k0 + r) * DMODEL + c4);
        }
        __syncthreads();

        float s[64];
#pragma unroll
        for (int j = 0; j < 64; j++) s[j] = 0.f;
#pragma unroll 1
        for (int d4 = 0; d4 < 64; d4 += 4) {
            float4 qv = *(const float4*)(Qs + t * QS_LD + d4);
#pragma unroll
            for (int j = 0; j < 64; j++) {
                float4 kv = *(const float4*)(Ks + j * 64 + d4);
                s[j] += qv.x * kv.x + qv.y * kv.y + qv.z * kv.z + qv.w * kv.w;
            }
        }

        if (k0 + 63 > qt) {
#pragma unroll
            for (int j = 0; j < 64; j++)
                if (k0 + j > q) s[j] = -1e30f;
        }

        float mt = -1e30f;
#pragma unroll
        for (int j = 0; j < 64; j++) mt = fmaxf(mt, s[j]);
        float mnew = fmaxf(mrow, mt);
        float alpha = __expf(mrow - mnew);
        mrow = mnew;
        lrow *= alpha;
#pragma unroll
        for (int i = 0; i < 16; i++) {
            O4[i].x *= alpha; O4[i].y *= alpha;
            O4[i].z *= alpha; O4[i].w *= alpha;
        }

        float pl[64];
        float lsum = 0.f;
#pragma unroll
        for (int j = 0; j < 64; j++) {
            float p = __expf(s[j] - mnew);
            pl[j] = p;
            lsum += p;
        }
        lrow += lsum;

#pragma unroll 1
        for (int j = 0; j < 64; j++) {
            float p = pl[j];
            const float* vrow = Vs + j * 64;
#pragma unroll
            for (int i = 0; i < 16; i++) {
                float4 v = *(const float4*)(vrow + i * 4);
                O4[i].x += p * v.x; O4[i].y += p * v.y;
                O4[i].z += p * v.z; O4[i].w += p * v.w;
            }
        }
    }

    const float inv = 1.f / lrow;
    float* AOg = g_AO + ((size_t)(b * TT + q)) * DMODEL + h * HDIM;
#pragma unroll
    for (int i = 0; i < 16; i++) {
        float4 o = O4[i];
        o.x *= inv; o.y *= inv; o.z *= inv; o.w *= inv;
        *(float4*)(AOg + i * 4) = o;
    }
}

// ---------------------------------------------------------------------------
// Launch
// ---------------------------------------------------------------------------
extern "C" void kernel_launch(void* const* d_in, const int* in_sizes, int n_in,
                              void* d_out, int out_size) {
    const float* x  = (const float*)d_in[0];
    const float* Wq = (const float*)d_in[1];
    const float* Wk = (const float*)d_in[2];
    const float* Wv = (const float*)d_in[3];
    const float* Wo = (const float*)d_in[4];
    float* out = (float*)d_out;

    cudaFuncSetAttribute(flash_kernel, cudaFuncAttributeMaxDynamicSharedMemorySize,
                         (int)FLASH_SMEM);

    dim3 gqkv(DMODEL / 128, (BB * TT) / 128, 3);
    qkv_kernel<<<gqkv, 256>>>(x, Wq, Wk, Wv);

    dim3 gatt(TT / 128, NHEAD, BB);
    flash_kernel<<<gatt, 128, FLASH_SMEM>>>();

    dim3 gout(DMODEL / 128, (BB * TT) / 128, 1);
    oproj_kernel<<<gout, 256>>>(Wo, out);
}

// round 9
// speedup vs baseline: 3.9550x; 2.9691x over previous
#include <cuda_runtime.h>
#include <cuda_bf16.h>
#include <cstdint>

// Problem constants
#define BB 2
#define TT 2048
#define DMODEL 1024
#define NHEAD 16
#define HDIM 64

// Scratch (device globals: allocation-free rule)
__device__ float g_Q[(size_t)BB * TT * DMODEL];
__device__ float g_K[(size_t)BB * TT * DMODEL];
__device__ float g_V[(size_t)BB * TT * DMODEL];
__device__ float g_AO[(size_t)BB * TT * DMODEL];

// ---------------------------------------------------------------------------
// Helpers
// ---------------------------------------------------------------------------
__device__ __forceinline__ uint32_t f2tf32(float f) {
    uint32_t u;
    asm("cvt.rna.tf32.f32 %0, %1;" : "=r"(u) : "f"(f));
    return u;
}

#define MMA_TF32(c, a, b)                                                     \
    asm volatile(                                                             \
        "mma.sync.aligned.m16n8k8.row.col.f32.tf32.tf32.f32 "                 \
        "{%0,%1,%2,%3}, {%4,%5,%6,%7}, {%8,%9}, {%0,%1,%2,%3};"               \
        : "+f"((c)[0]), "+f"((c)[1]), "+f"((c)[2]), "+f"((c)[3])              \
        : "r"((a)[0]), "r"((a)[1]), "r"((a)[2]), "r"((a)[3]),                 \
          "r"((b)[0]), "r"((b)[1]))

// ---------------------------------------------------------------------------
// TF32 mma.sync GEMM (NT): C[M,N] = A[M,K] * W[N,K]^T  (unchanged from R3)
// ---------------------------------------------------------------------------
#define SLD 36

__device__ __forceinline__ void gemm128_mma(const float* __restrict__ A,
                                            const float* __restrict__ W,
                                            float* __restrict__ C) {
    __shared__ uint32_t sA[128 * SLD];
    __shared__ uint32_t sB[128 * SLD];

    const int tid = threadIdx.x;
    const int wid = tid >> 5;
    const int lane = tid & 31;
    const int gid = lane >> 2;
    const int tig = lane & 3;

    const int wm = wid >> 2;
    const int wn = wid & 3;

    const int m0 = blockIdx.y * 128;
    const int n0 = blockIdx.x * 128;

    float acc[4][4][4];
#pragma unroll
    for (int mt = 0; mt < 4; mt++)
#pragma unroll
        for (int nt = 0; nt < 4; nt++)
#pragma unroll
            for (int r = 0; r < 4; r++) acc[mt][nt][r] = 0.f;

    const float* Ap = A + (size_t)m0 * DMODEL;
    const float* Wp = W + (size_t)n0 * DMODEL;

    for (int k0 = 0; k0 < DMODEL; k0 += 32) {
        __syncthreads();
#pragma unroll
        for (int i = 0; i < 4; i++) {
            int idx = i * 256 + tid;
            int r = idx >> 3;
            int c4 = (idx & 7) * 4;
            float4 av = *(const float4*)(Ap + (size_t)r * DMODEL + k0 + c4);
            float4 wv = *(const float4*)(Wp + (size_t)r * DMODEL + k0 + c4);
            uint4 at = make_uint4(f2tf32(av.x), f2tf32(av.y), f2tf32(av.z), f2tf32(av.w));
            uint4 wt = make_uint4(f2tf32(wv.x), f2tf32(wv.y), f2tf32(wv.z), f2tf32(wv.w));
            *(uint4*)(&sA[r * SLD + c4]) = at;
            *(uint4*)(&sB[r * SLD + c4]) = wt;
        }
        __syncthreads();

#pragma unroll
        for (int ks = 0; ks < 4; ks++) {
            const int kk = ks * 8;
            uint32_t af[4][4];
#pragma unroll
            for (int mt = 0; mt < 4; mt++) {
                int m = wm * 64 + mt * 16;
                af[mt][0] = sA[(m + gid) * SLD + kk + tig];
                af[mt][1] = sA[(m + 8 + gid) * SLD + kk + tig];
                af[mt][2] = sA[(m + gid) * SLD + kk + 4 + tig];
                af[mt][3] = sA[(m + 8 + gid) * SLD + kk + 4 + tig];
            }
            uint32_t bf[4][2];
#pragma unroll
            for (int nt = 0; nt < 4; nt++) {
                int n = wn * 32 + nt * 8;
                bf[nt][0] = sB[(n + gid) * SLD + kk + tig];
                bf[nt][1] = sB[(n + gid) * SLD + kk + 4 + tig];
            }
#pragma unroll
            for (int mt = 0; mt < 4; mt++)
#pragma unroll
                for (int nt = 0; nt < 4; nt++)
                    MMA_TF32(acc[mt][nt], af[mt], bf[nt]);
        }
    }

#pragma unroll
    for (int mt = 0; mt < 4; mt++) {
        int mbase = m0 + wm * 64 + mt * 16;
#pragma unroll
        for (int nt = 0; nt < 4; nt++) {
            int nbase = n0 + wn * 32 + nt * 8 + 2 * tig;
            float* C0 = C + (size_t)(mbase + gid) * DMODEL + nbase;
            float* C1 = C + (size_t)(mbase + 8 + gid) * DMODEL + nbase;
            *(float2*)C0 = make_float2(acc[mt][nt][0], acc[mt][nt][1]);
            *(float2*)C1 = make_float2(acc[mt][nt][2], acc[mt][nt][3]);
        }
    }
}

__global__ __launch_bounds__(256) void qkv_kernel(const float* __restrict__ x,
                                                  const float* __restrict__ Wq,
                                                  const float* __restrict__ Wk,
                                                  const float* __restrict__ Wv) {
    const float* W;
    float* C;
    if (blockIdx.z == 0)      { W = Wq; C = g_Q; }
    else if (blockIdx.z == 1) { W = Wk; C = g_K; }
    else                      { W = Wv; C = g_V; }
    gemm128_mma(x, W, C);
}

__global__ __launch_bounds__(256) void oproj_kernel(const float* __restrict__ Wo,
                                                    float* __restrict__ out) {
    gemm128_mma(g_AO, Wo, out);
}

// ---------------------------------------------------------------------------
// Flash attention (causal), tensorized tf32.
// Grid (32, 16, 2), 128 threads (4 warps x 16 q-rows). 64-key tiles.
// QK^T: compensated 3-mma tf32 (hi/lo split). PV: single tf32.
// ---------------------------------------------------------------------------
#define FLD 68  // padded smem row length (words); bank = 4*gid+tig (bijective)
#define FBUF (64 * FLD)
#define FLASH_SMEM (6 * FBUF * 4)

__global__ __launch_bounds__(128) void flash_mma_kernel() {
    extern __shared__ uint32_t dsm[];
    uint32_t* Qhi = dsm;
    uint32_t* Qlo = Qhi + FBUF;
    uint32_t* Khi = Qlo + FBUF;
    uint32_t* Klo = Khi + FBUF;
    uint32_t* Vs  = Klo + FBUF;
    uint32_t* Ps  = Vs + FBUF;

    const int tid = threadIdx.x;
    const int wid = tid >> 5;
    const int lane = tid & 31;
    const int gid = lane >> 2;
    const int tig = lane & 3;

    const int h = blockIdx.y;
    const int b = blockIdx.z;
    const int qtile = (TT / 64 - 1) - blockIdx.x;  // heavy CTAs first
    const int qt = qtile * 64;

    const float QSC = 0.125f * 1.44269504f;  // 1/sqrt(64) * log2(e)

    // Stage Q (scaled, hi/lo split)
    const float* Qg = g_Q + ((size_t)(b * TT + qt)) * DMODEL + h * HDIM;
#pragma unroll
    for (int i = 0; i < 8; i++) {
        int idx = i * 128 + tid;
        int r = idx >> 4;
        int c4 = (idx & 15) * 4;
        float4 v = *(const float4*)(Qg + (size_t)r * DMODEL + c4);
        float q0 = v.x * QSC, q1 = v.y * QSC, q2 = v.z * QSC, q3 = v.w * QSC;
        uint32_t h0 = f2tf32(q0), h1 = f2tf32(q1), h2 = f2tf32(q2), h3 = f2tf32(q3);
        uint32_t l0 = f2tf32(q0 - __uint_as_float(h0));
        uint32_t l1 = f2tf32(q1 - __uint_as_float(h1));
        uint32_t l2 = f2tf32(q2 - __uint_as_float(h2));
        uint32_t l3 = f2tf32(q3 - __uint_as_float(h3));
        *(uint4*)(&Qhi[r * FLD + c4]) = make_uint4(h0, h1, h2, h3);
        *(uint4*)(&Qlo[r * FLD + c4]) = make_uint4(l0, l1, l2, l3);
    }

    float O[8][4];
#pragma unroll
    for (int nt = 0; nt < 8; nt++)
#pragma unroll
        for (int r = 0; r < 4; r++) O[nt][r] = 0.f;
    float m2a = -1e30f, m2b = -1e30f, la = 0.f, lb = 0.f;

    const float* Kg = g_K + ((size_t)b * TT) * DMODEL + h * HDIM;
    const float* Vg = g_V + ((size_t)b * TT) * DMODEL + h * HDIM;

    const int nkt = qtile + 1;
    const int mrow = wid * 16;

    for (int kt = 0; kt < nkt; kt++) {
        const int k0 = kt * 64;

        __syncthreads();
#pragma unroll
        for (int i = 0; i < 8; i++) {
            int idx = i * 128 + tid;
            int r = idx >> 4;
            int c4 = (idx & 15) * 4;
            float4 kv = *(const float4*)(Kg + (size_t)(k0 + r) * DMODEL + c4);
            float4 vv = *(const float4*)(Vg + (size_t)(k0 + r) * DMODEL + c4);
            uint32_t h0 = f2tf32(kv.x), h1 = f2tf32(kv.y), h2 = f2tf32(kv.z), h3 = f2tf32(kv.w);
            uint32_t l0 = f2tf32(kv.x - __uint_as_float(h0));
            uint32_t l1 = f2tf32(kv.y - __uint_as_float(h1));
            uint32_t l2 = f2tf32(kv.z - __uint_as_float(h2));
            uint32_t l3 = f2tf32(kv.w - __uint_as_float(h3));
            *(uint4*)(&Khi[r * FLD + c4]) = make_uint4(h0, h1, h2, h3);
            *(uint4*)(&Klo[r * FLD + c4]) = make_uint4(l0, l1, l2, l3);
            *(uint4*)(&Vs[r * FLD + c4]) =
                make_uint4(f2tf32(vv.x), f2tf32(vv.y), f2tf32(vv.z), f2tf32(vv.w));
        }
        __syncthreads();

        // --- QK^T: compensated tf32 ---
        float S[8][4];
#pragma unroll
        for (int nt = 0; nt < 8; nt++)
#pragma unroll
            for (int r = 0; r < 4; r++) S[nt][r] = 0.f;

#pragma unroll
        for (int kk = 0; kk < 8; kk++) {
            const int kw = kk * 8;
            uint32_t ah[4], al[4];
            ah[0] = Qhi[(mrow + gid) * FLD + kw + tig];
            ah[1] = Qhi[(mrow + 8 + gid) * FLD + kw + tig];
            ah[2] = Qhi[(mrow + gid) * FLD + kw + 4 + tig];
            ah[3] = Qhi[(mrow + 8 + gid) * FLD + kw + 4 + tig];
            al[0] = Qlo[(mrow + gid) * FLD + kw + tig];
            al[1] = Qlo[(mrow + 8 + gid) * FLD + kw + tig];
            al[2] = Qlo[(mrow + gid) * FLD + kw + 4 + tig];
            al[3] = Qlo[(mrow + 8 + gid) * FLD + kw + 4 + tig];
#pragma unroll
            for (int nt = 0; nt < 8; nt++) {
                uint32_t bh[2], bl[2];
                bh[0] = Khi[(nt * 8 + gid) * FLD + kw + tig];
                bh[1] = Khi[(nt * 8 + gid) * FLD + kw + 4 + tig];
                bl[0] = Klo[(nt * 8 + gid) * FLD + kw + tig];
                bl[1] = Klo[(nt * 8 + gid) * FLD + kw + 4 + tig];
                MMA_TF32(S[nt], ah, bh);
                MMA_TF32(S[nt], ah, bl);
                MMA_TF32(S[nt], al, bh);
            }
        }

        // --- causal mask (diagonal tile only) ---
        if (kt == nkt - 1) {
            int qa = qt + mrow + gid;
            int qb = qa + 8;
#pragma unroll
            for (int nt = 0; nt < 8; nt++) {
                int kc = k0 + nt * 8 + 2 * tig;
                if (kc > qa)     S[nt][0] = -1e30f;
                if (kc + 1 > qa) S[nt][1] = -1e30f;
                if (kc > qb)     S[nt][2] = -1e30f;
                if (kc + 1 > qb) S[nt][3] = -1e30f;
            }
        }

        // --- online softmax (base 2) ---
        float ma = -1e30f, mb = -1e30f;
#pragma unroll
        for (int nt = 0; nt < 8; nt++) {
            ma = fmaxf(ma, fmaxf(S[nt][0], S[nt][1]));
            mb = fmaxf(mb, fmaxf(S[nt][2], S[nt][3]));
        }
        ma = fmaxf(ma, __shfl_xor_sync(0xFFFFFFFFu, ma, 1));
        ma = fmaxf(ma, __shfl_xor_sync(0xFFFFFFFFu, ma, 2));
        mb = fmaxf(mb, __shfl_xor_sync(0xFFFFFFFFu, mb, 1));
        mb = fmaxf(mb, __shfl_xor_sync(0xFFFFFFFFu, mb, 2));

        float mna = fmaxf(m2a, ma), mnb = fmaxf(m2b, mb);
        float alpa = exp2f(m2a - mna), alpb = exp2f(m2b - mnb);
        m2a = mna; m2b = mnb;
        la *= alpa; lb *= alpb;

        float pa = 0.f, pb = 0.f;
        const int ra = mrow + gid, rb = mrow + 8 + gid;
#pragma unroll
        for (int nt = 0; nt < 8; nt++) {
            float p0 = exp2f(S[nt][0] - mna), p1 = exp2f(S[nt][1] - mna);
            float p2 = exp2f(S[nt][2] - mnb), p3 = exp2f(S[nt][3] - mnb);
            pa += p0 + p1; pb += p2 + p3;
            O[nt][0] *= alpa; O[nt][1] *= alpa;
            O[nt][2] *= alpb; O[nt][3] *= alpb;
            *(uint2*)(&Ps[ra * FLD + nt * 8 + 2 * tig]) =
                make_uint2(f2tf32(p0), f2tf32(p1));
            *(uint2*)(&Ps[rb * FLD + nt * 8 + 2 * tig]) =
                make_uint2(f2tf32(p2), f2tf32(p3));
        }
        pa += __shfl_xor_sync(0xFFFFFFFFu, pa, 1);
        pa += __shfl_xor_sync(0xFFFFFFFFu, pa, 2);
        pb += __shfl_xor_sync(0xFFFFFFFFu, pb, 1);
        pb += __shfl_xor_sync(0xFFFFFFFFu, pb, 2);
        la += pa; lb += pb;

        __syncwarp();

        // --- PV: O += P * V ---
#pragma unroll
        for (int kk = 0; kk < 8; kk++) {
            const int kw = kk * 8;
            uint32_t av[4];
            av[0] = Ps[ra * FLD + kw + tig];
            av[1] = Ps[rb * FLD + kw + tig];
            av[2] = Ps[ra * FLD + kw + 4 + tig];
            av[3] = Ps[rb * FLD + kw + 4 + tig];
#pragma unroll
            for (int nt = 0; nt < 8; nt++) {
                uint32_t bv[2];
                bv[0] = Vs[(kw + tig) * FLD + nt * 8 + gid];
                bv[1] = Vs[(kw + 4 + tig) * FLD + nt * 8 + gid];
                MMA_TF32(O[nt], av, bv);
            }
        }
    }

    // Epilogue
    const float inva = 1.f / la, invb = 1.f / lb;
    const int ra = qt + mrow + gid, rb = ra + 8;
    float* Oa = g_AO + ((size_t)(b * TT + ra)) * DMODEL + h * HDIM;
    float* Ob = g_AO + ((size_t)(b * TT + rb)) * DMODEL + h * HDIM;
#pragma unroll
    for (int nt = 0; nt < 8; nt++) {
        *(float2*)(Oa + nt * 8 + 2 * tig) =
            make_float2(O[nt][0] * inva, O[nt][1] * inva);
        *(float2*)(Ob + nt * 8 + 2 * tig) =
            make_float2(O[nt][2] * invb, O[nt][3] * invb);
    }
}

// ---------------------------------------------------------------------------
// Launch
// ---------------------------------------------------------------------------
extern "C" void kernel_launch(void* const* d_in, const int* in_sizes, int n_in,
                              void* d_out, int out_size) {
    const float* x  = (const float*)d_in[0];
    const float* Wq = (const float*)d_in[1];
    const float* Wk = (const float*)d_in[2];
    const float* Wv = (const float*)d_in[3];
    const float* Wo = (const float*)d_in[4];
    float* out = (float*)d_out;

    cudaFuncSetAttribute(flash_mma_kernel, cudaFuncAttributeMaxDynamicSharedMemorySize,
                         (int)FLASH_SMEM);

    dim3 gqkv(DMODEL / 128, (BB * TT) / 128, 3);
    qkv_kernel<<<gqkv, 256>>>(x, Wq, Wk, Wv);

    dim3 gatt(TT / 64, NHEAD, BB);
    flash_mma_kernel<<<gatt, 128, FLASH_SMEM>>>();

    dim3 gout(DMODEL / 128, (BB * TT) / 128, 1);
    oproj_kernel<<<gout, 256>>>(Wo, out);
}

// round 10
// speedup vs baseline: 3.9978x; 1.0108x over previous
#include <cuda_runtime.h>
#include <cuda_bf16.h>
#include <cstdint>

// Problem constants
#define BB 2
#define TT 2048
#define DMODEL 1024
#define NHEAD 16
#define HDIM 64

// Scratch (device globals: allocation-free rule)
__device__ float g_Q[(size_t)BB * TT * DMODEL];
__device__ float g_K[(size_t)BB * TT * DMODEL];
__device__ float g_V[(size_t)BB * TT * DMODEL];
__device__ float g_AO[(size_t)BB * TT * DMODEL];

// ---------------------------------------------------------------------------
// Helpers
// ---------------------------------------------------------------------------
__device__ __forceinline__ uint32_t f2tf32(float f) {
    uint32_t u;
    asm("cvt.rna.tf32.f32 %0, %1;" : "=r"(u) : "f"(f));
    return u;
}

__device__ __forceinline__ uint32_t smem_u32(const void* p) {
    uint32_t a;
    asm("{ .reg .u64 t; cvta.to.shared.u64 t, %1; cvt.u32.u64 %0, t; }"
        : "=r"(a) : "l"(p));
    return a;
}

__device__ __forceinline__ void cp16(uint32_t dst, const void* src) {
    asm volatile("cp.async.cg.shared.global [%0], [%1], 16;"
                 :: "r"(dst), "l"(src) : "memory");
}
__device__ __forceinline__ void cp_commit() {
    asm volatile("cp.async.commit_group;" ::: "memory");
}
__device__ __forceinline__ void cp_wait0() {
    asm volatile("cp.async.wait_group 0;" ::: "memory");
}

#define MMA_TF32(c, a, b)                                                     \
    asm volatile(                                                             \
        "mma.sync.aligned.m16n8k8.row.col.f32.tf32.tf32.f32 "                 \
        "{%0,%1,%2,%3}, {%4,%5,%6,%7}, {%8,%9}, {%0,%1,%2,%3};"               \
        : "+f"((c)[0]), "+f"((c)[1]), "+f"((c)[2]), "+f"((c)[3])              \
        : "r"((a)[0]), "r"((a)[1]), "r"((a)[2]), "r"((a)[3]),                 \
          "r"((b)[0]), "r"((b)[1]))

// ---------------------------------------------------------------------------
// TF32 mma.sync GEMM (NT) with cp.async raw-staging pipeline.
// C[M,N] = A[M,K] * W[N,K]^T. CTA 128x128, 256 thr (2m x 4n warps), BK=32.
// ---------------------------------------------------------------------------
#define SLD 36
#define KCHUNKS (DMODEL / 32)
#define GEMM_SMEM ((2 * 128 * SLD + 2 * 128 * 32) * 4)

__device__ __forceinline__ void gemm128_mma(const float* __restrict__ A,
                                            const float* __restrict__ W,
                                            float* __restrict__ C) {
    extern __shared__ uint32_t gsm[];
    uint32_t* sA = gsm;                       // 128 x SLD (tf32)
    uint32_t* sB = sA + 128 * SLD;
    float* rawA = (float*)(sB + 128 * SLD);   // 128 x 32 (raw fp32)
    float* rawB = rawA + 128 * 32;
    const uint32_t rawA_u = smem_u32(rawA);
    const uint32_t rawB_u = smem_u32(rawB);

    const int tid = threadIdx.x;
    const int wid = tid >> 5;
    const int lane = tid & 31;
    const int gid = lane >> 2;
    const int tig = lane & 3;
    const int wm = wid >> 2;
    const int wn = wid & 3;

    const int m0 = blockIdx.y * 128;
    const int n0 = blockIdx.x * 128;

    float acc[4][4][4];
#pragma unroll
    for (int mt = 0; mt < 4; mt++)
#pragma unroll
        for (int nt = 0; nt < 4; nt++)
#pragma unroll
            for (int r = 0; r < 4; r++) acc[mt][nt][r] = 0.f;

    const float* Ap = A + (size_t)m0 * DMODEL;
    const float* Wp = W + (size_t)n0 * DMODEL;

    // Prologue: async-copy chunk 0
#pragma unroll
    for (int i = 0; i < 4; i++) {
        int idx = i * 256 + tid;
        int r = idx >> 3;
        int c4 = (idx & 7) * 4;
        cp16(rawA_u + (r * 32 + c4) * 4, Ap + (size_t)r * DMODEL + c4);
        cp16(rawB_u + (r * 32 + c4) * 4, Wp + (size_t)r * DMODEL + c4);
    }
    cp_commit();

    for (int kc = 0; kc < KCHUNKS; kc++) {
        cp_wait0();
        __syncthreads();   // raw ready for all; previous mma done (operand free)

        // Convert raw fp32 -> tf32 operand tiles (pure smem)
#pragma unroll
        for (int i = 0; i < 4; i++) {
            int idx = i * 256 + tid;
            int r = idx >> 3;
            int c4 = (idx & 7) * 4;
            float4 av = *(const float4*)(rawA + r * 32 + c4);
            float4 wv = *(const float4*)(rawB + r * 32 + c4);
            *(uint4*)(&sA[r * SLD + c4]) =
                make_uint4(f2tf32(av.x), f2tf32(av.y), f2tf32(av.z), f2tf32(av.w));
            *(uint4*)(&sB[r * SLD + c4]) =
                make_uint4(f2tf32(wv.x), f2tf32(wv.y), f2tf32(wv.z), f2tf32(wv.w));
        }
        __syncthreads();   // operands ready; raw free for next copy

        // Issue next chunk's async copy (overlaps with mma below)
        if (kc + 1 < KCHUNKS) {
            const int kn = (kc + 1) * 32;
#pragma unroll
            for (int i = 0; i < 4; i++) {
                int idx = i * 256 + tid;
                int r = idx >> 3;
                int c4 = (idx & 7) * 4;
                cp16(rawA_u + (r * 32 + c4) * 4, Ap + (size_t)r * DMODEL + kn + c4);
                cp16(rawB_u + (r * 32 + c4) * 4, Wp + (size_t)r * DMODEL + kn + c4);
            }
            cp_commit();
        }

#pragma unroll
        for (int ks = 0; ks < 4; ks++) {
            const int kk = ks * 8;
            uint32_t af[4][4];
#pragma unroll
            for (int mt = 0; mt < 4; mt++) {
                int m = wm * 64 + mt * 16;
                af[mt][0] = sA[(m + gid) * SLD + kk + tig];
                af[mt][1] = sA[(m + 8 + gid) * SLD + kk + tig];
                af[mt][2] = sA[(m + gid) * SLD + kk + 4 + tig];
                af[mt][3] = sA[(m + 8 + gid) * SLD + kk + 4 + tig];
            }
            uint32_t bf[4][2];
#pragma unroll
            for (int nt = 0; nt < 4; nt++) {
                int n = wn * 32 + nt * 8;
                bf[nt][0] = sB[(n + gid) * SLD + kk + tig];
                bf[nt][1] = sB[(n + gid) * SLD + kk + 4 + tig];
            }
#pragma unroll
            for (int mt = 0; mt < 4; mt++)
#pragma unroll
                for (int nt = 0; nt < 4; nt++)
                    MMA_TF32(acc[mt][nt], af[mt], bf[nt]);
        }
    }

#pragma unroll
    for (int mt = 0; mt < 4; mt++) {
        int mbase = m0 + wm * 64 + mt * 16;
#pragma unroll
        for (int nt = 0; nt < 4; nt++) {
            int nbase = n0 + wn * 32 + nt * 8 + 2 * tig;
            float* C0 = C + (size_t)(mbase + gid) * DMODEL + nbase;
            float* C1 = C + (size_t)(mbase + 8 + gid) * DMODEL + nbase;
            *(float2*)C0 = make_float2(acc[mt][nt][0], acc[mt][nt][1]);
            *(float2*)C1 = make_float2(acc[mt][nt][2], acc[mt][nt][3]);
        }
    }
}

__global__ __launch_bounds__(256) void qkv_kernel(const float* __restrict__ x,
                                                  const float* __restrict__ Wq,
                                                  const float* __restrict__ Wk,
                                                  const float* __restrict__ Wv) {
    const float* W;
    float* C;
    if (blockIdx.z == 0)      { W = Wq; C = g_Q; }
    else if (blockIdx.z == 1) { W = Wk; C = g_K; }
    else                      { W = Wv; C = g_V; }
    gemm128_mma(x, W, C);
}

__global__ __launch_bounds__(256) void oproj_kernel(const float* __restrict__ Wo,
                                                    float* __restrict__ out) {
    gemm128_mma(g_AO, Wo, out);
}

// ---------------------------------------------------------------------------
// Flash attention (causal), tensorized tf32, cp.async pipelined.
// Grid (32,16,2), 128 thr (4 warps x 16 q-rows), 64-key tiles.
// QK^T: compensated 3-mma tf32, Q fragments held in registers.
// ---------------------------------------------------------------------------
#define FLD 68
#define FBUF (64 * FLD)
#define FLASH_SMEM ((4 * FBUF + 2 * 64 * 64) * 4)

__global__ __launch_bounds__(128) void flash_mma_kernel() {
    extern __shared__ uint32_t dsm[];
    uint32_t* Khi = dsm;
    uint32_t* Klo = Khi + FBUF;
    uint32_t* Vs  = Klo + FBUF;
    uint32_t* Ps  = Vs + FBUF;
    float* rawK = (float*)(Ps + FBUF);     // 64 x 64 raw fp32
    float* rawV = rawK + 64 * 64;
    const uint32_t rawK_u = smem_u32(rawK);
    const uint32_t rawV_u = smem_u32(rawV);

    const int tid = threadIdx.x;
    const int wid = tid >> 5;
    const int lane = tid & 31;
    const int gid = lane >> 2;
    const int tig = lane & 3;

    const int h = blockIdx.y;
    const int b = blockIdx.z;
    const int qtile = (TT / 64 - 1) - blockIdx.x;  // heavy CTAs first
    const int qt = qtile * 64;
    const int nkt = qtile + 1;
    const int mrow = wid * 16;

    const float QSC = 0.125f * 1.44269504f;  // 1/sqrt(64) * log2(e)

    const float* Kg = g_K + ((size_t)b * TT) * DMODEL + h * HDIM;
    const float* Vg = g_V + ((size_t)b * TT) * DMODEL + h * HDIM;

    // Kick off tile 0 K/V copy first (overlaps with Q staging)
#pragma unroll
    for (int i = 0; i < 8; i++) {
        int idx = i * 128 + tid;
        int r = idx >> 4;
        int c4 = (idx & 15) * 4;
        cp16(rawK_u + (r * 64 + c4) * 4, Kg + (size_t)r * DMODEL + c4);
        cp16(rawV_u + (r * 64 + c4) * 4, Vg + (size_t)r * DMODEL + c4);
    }
    cp_commit();

    // Stage scaled Q (fp32) into Ps region, then gather hi/lo fragments to regs
    float* Qstage = (float*)Ps;
    const float* Qg = g_Q + ((size_t)(b * TT + qt)) * DMODEL + h * HDIM;
#pragma unroll
    for (int i = 0; i < 8; i++) {
        int idx = i * 128 + tid;
        int r = idx >> 4;
        int c4 = (idx & 15) * 4;
        float4 v = *(const float4*)(Qg + (size_t)r * DMODEL + c4);
        v.x *= QSC; v.y *= QSC; v.z *= QSC; v.w *= QSC;
        *(float4*)(&Qstage[r * FLD + c4]) = v;
    }
    __syncthreads();

    uint32_t qah[8][4], qal[8][4];
#pragma unroll
    for (int kk = 0; kk < 8; kk++) {
        const int kw = kk * 8;
        float q0 = Qstage[(mrow + gid) * FLD + kw + tig];
        float q1 = Qstage[(mrow + 8 + gid) * FLD + kw + tig];
        float q2 = Qstage[(mrow + gid) * FLD + kw + 4 + tig];
        float q3 = Qstage[(mrow + 8 + gid) * FLD + kw + 4 + tig];
        qah[kk][0] = f2tf32(q0); qal[kk][0] = f2tf32(q0 - __uint_as_float(qah[kk][0]));
        qah[kk][1] = f2tf32(q1); qal[kk][1] = f2tf32(q1 - __uint_as_float(qah[kk][1]));
        qah[kk][2] = f2tf32(q2); qal[kk][2] = f2tf32(q2 - __uint_as_float(qah[kk][2]));
        qah[kk][3] = f2tf32(q3); qal[kk][3] = f2tf32(q3 - __uint_as_float(qah[kk][3]));
    }

    float O[8][4];
#pragma unroll
    for (int nt = 0; nt < 8; nt++)
#pragma unroll
        for (int r = 0; r < 4; r++) O[nt][r] = 0.f;
    float m2a = -1e30f, m2b = -1e30f, la = 0.f, lb = 0.f;

    for (int kt = 0; kt < nkt; kt++) {
        cp_wait0();
        __syncthreads();   // raw K/V ready; Khi/Klo/Vs/Ps free (prev tile done)

        // Convert raw -> Khi/Klo (hi/lo split) and Vs (tf32)
#pragma unroll
        for (int i = 0; i < 8; i++) {
            int idx = i * 128 + tid;
            int r = idx >> 4;
            int c4 = (idx & 15) * 4;
            float4 kv = *(const float4*)(rawK + r * 64 + c4);
            float4 vv = *(const float4*)(rawV + r * 64 + c4);
            uint32_t h0 = f2tf32(kv.x), h1 = f2tf32(kv.y), h2 = f2tf32(kv.z), h3 = f2tf32(kv.w);
            uint32_t l0 = f2tf32(kv.x - __uint_as_float(h0));
            uint32_t l1 = f2tf32(kv.y - __uint_as_float(h1));
            uint32_t l2 = f2tf32(kv.z - __uint_as_float(h2));
            uint32_t l3 = f2tf32(kv.w - __uint_as_float(h3));
            *(uint4*)(&Khi[r * FLD + c4]) = make_uint4(h0, h1, h2, h3);
            *(uint4*)(&Klo[r * FLD + c4]) = make_uint4(l0, l1, l2, l3);
            *(uint4*)(&Vs[r * FLD + c4]) =
                make_uint4(f2tf32(vv.x), f2tf32(vv.y), f2tf32(vv.z), f2tf32(vv.w));
        }
        __syncthreads();   // operands ready; raw free

        // Issue next tile's copy (overlaps with QK/softmax/PV below)
        if (kt + 1 < nkt) {
            const int kn = (kt + 1) * 64;
#pragma unroll
            for (int i = 0; i < 8; i++) {
                int idx = i * 128 + tid;
                int r = idx >> 4;
                int c4 = (idx & 15) * 4;
                cp16(rawK_u + (r * 64 + c4) * 4, Kg + (size_t)(kn + r) * DMODEL + c4);
                cp16(rawV_u + (r * 64 + c4) * 4, Vg + (size_t)(kn + r) * DMODEL + c4);
            }
            cp_commit();
        }

        // --- QK^T: compensated tf32, A from registers ---
        float S[8][4];
#pragma unroll
        for (int nt = 0; nt < 8; nt++)
#pragma unroll
            for (int r = 0; r < 4; r++) S[nt][r] = 0.f;

#pragma unroll
        for (int kk = 0; kk < 8; kk++) {
            const int kw = kk * 8;
#pragma unroll
            for (int nt = 0; nt < 8; nt++) {
                uint32_t bh[2], bl[2];
                bh[0] = Khi[(nt * 8 + gid) * FLD + kw + tig];
                bh[1] = Khi[(nt * 8 + gid) * FLD + kw + 4 + tig];
                bl[0] = Klo[(nt * 8 + gid) * FLD + kw + tig];
                bl[1] = Klo[(nt * 8 + gid) * FLD + kw + 4 + tig];
                MMA_TF32(S[nt], qah[kk], bh);
                MMA_TF32(S[nt], qah[kk], bl);
                MMA_TF32(S[nt], qal[kk], bh);
            }
        }

        // --- causal mask (diagonal tile only) ---
        const int k0 = kt * 64;
        if (kt == nkt - 1) {
            int qa = qt + mrow + gid;
            int qb = qa + 8;
#pragma unroll
            for (int nt = 0; nt < 8; nt++) {
                int kc = k0 + nt * 8 + 2 * tig;
                if (kc > qa)     S[nt][0] = -1e30f;
                if (kc + 1 > qa) S[nt][1] = -1e30f;
                if (kc > qb)     S[nt][2] = -1e30f;
                if (kc + 1 > qb) S[nt][3] = -1e30f;
            }
        }

        // --- online softmax (base 2) ---
        float ma = -1e30f, mb = -1e30f;
#pragma unroll
        for (int nt = 0; nt < 8; nt++) {
            ma = fmaxf(ma, fmaxf(S[nt][0], S[nt][1]));
            mb = fmaxf(mb, fmaxf(S[nt][2], S[nt][3]));
        }
        ma = fmaxf(ma, __shfl_xor_sync(0xFFFFFFFFu, ma, 1));
        ma = fmaxf(ma, __shfl_xor_sync(0xFFFFFFFFu, ma, 2));
        mb = fmaxf(mb, __shfl_xor_sync(0xFFFFFFFFu, mb, 1));
        mb = fmaxf(mb, __shfl_xor_sync(0xFFFFFFFFu, mb, 2));

        float mna = fmaxf(m2a, ma), mnb = fmaxf(m2b, mb);
        float alpa = exp2f(m2a - mna), alpb = exp2f(m2b - mnb);
        m2a = mna; m2b = mnb;
        la *= alpa; lb *= alpb;

        float pa = 0.f, pb = 0.f;
        const int ra = mrow + gid, rb = mrow + 8 + gid;
#pragma unroll
        for (int nt = 0; nt < 8; nt++) {
            float p0 = exp2f(S[nt][0] - mna), p1 = exp2f(S[nt][1] - mna);
            float p2 = exp2f(S[nt][2] - mnb), p3 = exp2f(S[nt][3] - mnb);
            pa += p0 + p1; pb += p2 + p3;
            O[nt][0] *= alpa; O[nt][1] *= alpa;
            O[nt][2] *= alpb; O[nt][3] *= alpb;
            *(uint2*)(&Ps[ra * FLD + nt * 8 + 2 * tig]) =
                make_uint2(f2tf32(p0), f2tf32(p1));
            *(uint2*)(&Ps[rb * FLD + nt * 8 + 2 * tig]) =
                make_uint2(f2tf32(p2), f2tf32(p3));
        }
        pa += __shfl_xor_sync(0xFFFFFFFFu, pa, 1);
        pa += __shfl_xor_sync(0xFFFFFFFFu, pa, 2);
        pb += __shfl_xor_sync(0xFFFFFFFFu, pb, 1);
        pb += __shfl_xor_sync(0xFFFFFFFFu, pb, 2);
        la += pa; lb += pb;

        __syncwarp();

        // --- PV: O += P * V ---
#pragma unroll
        for (int kk = 0; kk < 8; kk++) {
            const int kw = kk * 8;
            uint32_t av[4];
            av[0] = Ps[ra * FLD + kw + tig];
            av[1] = Ps[rb * FLD + kw + tig];
            av[2] = Ps[ra * FLD + kw + 4 + tig];
            av[3] = Ps[rb * FLD + kw + 4 + tig];
#pragma unroll
            for (int nt = 0; nt < 8; nt++) {
                uint32_t bv[2];
                bv[0] = Vs[(kw + tig) * FLD + nt * 8 + gid];
                bv[1] = Vs[(kw + 4 + tig) * FLD + nt * 8 + gid];
                MMA_TF32(O[nt], av, bv);
            }
        }
    }

    // Epilogue
    const float inva = 1.f / la, invb = 1.f / lb;
    const int ra = qt + mrow + gid, rb = ra + 8;
    float* Oa = g_AO + ((size_t)(b * TT + ra)) * DMODEL + h * HDIM;
    float* Ob = g_AO + ((size_t)(b * TT + rb)) * DMODEL + h * HDIM;
#pragma unroll
    for (int nt = 0; nt < 8; nt++) {
        *(float2*)(Oa + nt * 8 + 2 * tig) =
            make_float2(O[nt][0] * inva, O[nt][1] * inva);
        *(float2*)(Ob + nt * 8 + 2 * tig) =
            make_float2(O[nt][2] * invb, O[nt][3] * invb);
    }
}

// ---------------------------------------------------------------------------
// Launch
// ---------------------------------------------------------------------------
extern "C" void kernel_launch(void* const* d_in, const int* in_sizes, int n_in,
                              void* d_out, int out_size) {
    const float* x  = (const float*)d_in[0];
    const float* Wq = (const float*)d_in[1];
    const float* Wk = (const float*)d_in[2];
    const float* Wv = (const float*)d_in[3];
    const float* Wo = (const float*)d_in[4];
    float* out = (float*)d_out;

    cudaFuncSetAttribute(qkv_kernel, cudaFuncAttributeMaxDynamicSharedMemorySize,
                         (int)GEMM_SMEM);
    cudaFuncSetAttribute(oproj_kernel, cudaFuncAttributeMaxDynamicSharedMemorySize,
                         (int)GEMM_SMEM);
    cudaFuncSetAttribute(flash_mma_kernel, cudaFuncAttributeMaxDynamicSharedMemorySize,
                         (int)FLASH_SMEM);

    dim3 gqkv(DMODEL / 128, (BB * TT) / 128, 3);
    qkv_kernel<<<gqkv, 256, GEMM_SMEM>>>(x, Wq, Wk, Wv);

    dim3 gatt(TT / 64, NHEAD, BB);
    flash_mma_kernel<<<gatt, 128, FLASH_SMEM>>>();

    dim3 gout(DMODEL / 128, (BB * TT) / 128, 1);
    oproj_kernel<<<gout, 256, GEMM_SMEM>>>(Wo, out);
}

// round 12
// speedup vs baseline: 4.5564x; 1.1397x over previous
#include <cuda_runtime.h>
#include <cuda_bf16.h>
#include <cstdint>

// Problem constants
#define BB 2
#define TT 2048
#define DMODEL 1024
#define NHEAD 16
#define HDIM 64

// Scratch (device globals: allocation-free rule)
__device__ float g_Q[(size_t)BB * TT * DMODEL];
__device__ float g_K[(size_t)BB * TT * DMODEL];
__device__ float g_V[(size_t)BB * TT * DMODEL];
__device__ float g_AO[(size_t)BB * TT * DMODEL];

// ---------------------------------------------------------------------------
// Helpers
// ---------------------------------------------------------------------------
__device__ __forceinline__ uint32_t f2tf32(float f) {
    uint32_t u;
    asm("cvt.rna.tf32.f32 %0, %1;" : "=r"(u) : "f"(f));
    return u;
}

__device__ __forceinline__ uint32_t smem_u32(const void* p) {
    uint32_t a;
    asm("{ .reg .u64 t; cvta.to.shared.u64 t, %1; cvt.u32.u64 %0, t; }"
        : "=r"(a) : "l"(p));
    return a;
}

__device__ __forceinline__ void cp16(uint32_t dst, const void* src) {
    asm volatile("cp.async.cg.shared.global [%0], [%1], 16;"
                 :: "r"(dst), "l"(src) : "memory");
}
__device__ __forceinline__ void cp_commit() {
    asm volatile("cp.async.commit_group;" ::: "memory");
}
__device__ __forceinline__ void cp_wait0() {
    asm volatile("cp.async.wait_group 0;" ::: "memory");
}

// pack two floats -> bf16x2 word (x low half, y high half)
__device__ __forceinline__ uint32_t pk_bf16(float x, float y) {
    __nv_bfloat162 h = __float22bfloat162_rn(make_float2(x, y));
    return *reinterpret_cast<uint32_t*>(&h);
}
__device__ __forceinline__ float bf_lo(uint32_t w) {
    __nv_bfloat162 h = *reinterpret_cast<__nv_bfloat162*>(&w);
    return __bfloat162float(h.x);
}
__device__ __forceinline__ float bf_hi(uint32_t w) {
    __nv_bfloat162 h = *reinterpret_cast<__nv_bfloat162*>(&w);
    return __bfloat162float(h.y);
}

#define MMA_TF32(c, a, b)                                                     \
    asm volatile(                                                             \
        "mma.sync.aligned.m16n8k8.row.col.f32.tf32.tf32.f32 "                 \
        "{%0,%1,%2,%3}, {%4,%5,%6,%7}, {%8,%9}, {%0,%1,%2,%3};"               \
        : "+f"((c)[0]), "+f"((c)[1]), "+f"((c)[2]), "+f"((c)[3])              \
        : "r"((a)[0]), "r"((a)[1]), "r"((a)[2]), "r"((a)[3]),                 \
          "r"((b)[0]), "r"((b)[1]))

#define MMA_BF16(c, a, b)                                                     \
    asm volatile(                                                             \
        "mma.sync.aligned.m16n8k16.row.col.f32.bf16.bf16.f32 "                \
        "{%0,%1,%2,%3}, {%4,%5,%6,%7}, {%8,%9}, {%0,%1,%2,%3};"               \
        : "+f"((c)[0]), "+f"((c)[1]), "+f"((c)[2]), "+f"((c)[3])              \
        : "r"((a)[0]), "r"((a)[1]), "r"((a)[2]), "r"((a)[3]),                 \
          "r"((b)[0]), "r"((b)[1]))

// ---------------------------------------------------------------------------
// TF32 mma.sync GEMM (NT) with cp.async raw-staging pipeline (unchanged).
// ---------------------------------------------------------------------------
#define SLD 36
#define KCHUNKS (DMODEL / 32)
#define GEMM_SMEM ((2 * 128 * SLD + 2 * 128 * 32) * 4)

__device__ __forceinline__ void gemm128_mma(const float* __restrict__ A,
                                            const float* __restrict__ W,
                                            float* __restrict__ C) {
    extern __shared__ uint32_t gsm[];
    uint32_t* sA = gsm;
    uint32_t* sB = sA + 128 * SLD;
    float* rawA = (float*)(sB + 128 * SLD);
    float* rawB = rawA + 128 * 32;
    const uint32_t rawA_u = smem_u32(rawA);
    const uint32_t rawB_u = smem_u32(rawB);

    const int tid = threadIdx.x;
    const int wid = tid >> 5;
    const int lane = tid & 31;
    const int gid = lane >> 2;
    const int tig = lane & 3;
    const int wm = wid >> 2;
    const int wn = wid & 3;

    const int m0 = blockIdx.y * 128;
    const int n0 = blockIdx.x * 128;

    float acc[4][4][4];
#pragma unroll
    for (int mt = 0; mt < 4; mt++)
#pragma unroll
        for (int nt = 0; nt < 4; nt++)
#pragma unroll
            for (int r = 0; r < 4; r++) acc[mt][nt][r] = 0.f;

    const float* Ap = A + (size_t)m0 * DMODEL;
    const float* Wp = W + (size_t)n0 * DMODEL;

#pragma unroll
    for (int i = 0; i < 4; i++) {
        int idx = i * 256 + tid;
        int r = idx >> 3;
        int c4 = (idx & 7) * 4;
        cp16(rawA_u + (r * 32 + c4) * 4, Ap + (size_t)r * DMODEL + c4);
        cp16(rawB_u + (r * 32 + c4) * 4, Wp + (size_t)r * DMODEL + c4);
    }
    cp_commit();

    for (int kc = 0; kc < KCHUNKS; kc++) {
        cp_wait0();
        __syncthreads();

#pragma unroll
        for (int i = 0; i < 4; i++) {
            int idx = i * 256 + tid;
            int r = idx >> 3;
            int c4 = (idx & 7) * 4;
            float4 av = *(const float4*)(rawA + r * 32 + c4);
            float4 wv = *(const float4*)(rawB + r * 32 + c4);
            *(uint4*)(&sA[r * SLD + c4]) =
                make_uint4(f2tf32(av.x), f2tf32(av.y), f2tf32(av.z), f2tf32(av.w));
            *(uint4*)(&sB[r * SLD + c4]) =
                make_uint4(f2tf32(wv.x), f2tf32(wv.y), f2tf32(wv.z), f2tf32(wv.w));
        }
        __syncthreads();

        if (kc + 1 < KCHUNKS) {
            const int kn = (kc + 1) * 32;
#pragma unroll
            for (int i = 0; i < 4; i++) {
                int idx = i * 256 + tid;
                int r = idx >> 3;
                int c4 = (idx & 7) * 4;
                cp16(rawA_u + (r * 32 + c4) * 4, Ap + (size_t)r * DMODEL + kn + c4);
                cp16(rawB_u + (r * 32 + c4) * 4, Wp + (size_t)r * DMODEL + kn + c4);
            }
            cp_commit();
        }

#pragma unroll
        for (int ks = 0; ks < 4; ks++) {
            const int kk = ks * 8;
            uint32_t af[4][4];
#pragma unroll
            for (int mt = 0; mt < 4; mt++) {
                int m = wm * 64 + mt * 16;
                af[mt][0] = sA[(m + gid) * SLD + kk + tig];
                af[mt][1] = sA[(m + 8 + gid) * SLD + kk + tig];
                af[mt][2] = sA[(m + gid) * SLD + kk + 4 + tig];
                af[mt][3] = sA[(m + 8 + gid) * SLD + kk + 4 + tig];
            }
            uint32_t bf[4][2];
#pragma unroll
            for (int nt = 0; nt < 4; nt++) {
                int n = wn * 32 + nt * 8;
                bf[nt][0] = sB[(n + gid) * SLD + kk + tig];
                bf[nt][1] = sB[(n + gid) * SLD + kk + 4 + tig];
            }
#pragma unroll
            for (int mt = 0; mt < 4; mt++)
#pragma unroll
                for (int nt = 0; nt < 4; nt++)
                    MMA_TF32(acc[mt][nt], af[mt], bf[nt]);
        }
    }

#pragma unroll
    for (int mt = 0; mt < 4; mt++) {
        int mbase = m0 + wm * 64 + mt * 16;
#pragma unroll
        for (int nt = 0; nt < 4; nt++) {
            int nbase = n0 + wn * 32 + nt * 8 + 2 * tig;
            float* C0 = C + (size_t)(mbase + gid) * DMODEL + nbase;
            float* C1 = C + (size_t)(mbase + 8 + gid) * DMODEL + nbase;
            *(float2*)C0 = make_float2(acc[mt][nt][0], acc[mt][nt][1]);
            *(float2*)C1 = make_float2(acc[mt][nt][2], acc[mt][nt][3]);
        }
    }
}

__global__ __launch_bounds__(256) void qkv_kernel(const float* __restrict__ x,
                                                  const float* __restrict__ Wq,
                                                  const float* __restrict__ Wk,
                                                  const float* __restrict__ Wv) {
    const float* W;
    float* C;
    if (blockIdx.z == 0)      { W = Wq; C = g_Q; }
    else if (blockIdx.z == 1) { W = Wk; C = g_K; }
    else                      { W = Wv; C = g_V; }
    gemm128_mma(x, W, C);
}

__global__ __launch_bounds__(256) void oproj_kernel(const float* __restrict__ Wo,
                                                    float* __restrict__ out) {
    gemm128_mma(g_AO, Wo, out);
}

// ---------------------------------------------------------------------------
// Flash attention (causal): QK^T = compensated bf16 m16n8k16, PV = tf32.
// Grid (32,16,2), 128 thr (4 warps x 16 q-rows), 64-key tiles.
// ---------------------------------------------------------------------------
#define FLD 68   // tf32/fp32 buffers row stride (words)
#define KLD 36   // bf16-pair buffers row stride (words)
#define FLASH_SMEM ((2 * 64 * KLD + 2 * 64 * FLD + 2 * 64 * 64) * 4)

__global__ __launch_bounds__(128) void flash_mma_kernel() {
    extern __shared__ uint32_t dsm[];
    uint32_t* Khb = dsm;                    // 64 x KLD bf16-pairs (hi)
    uint32_t* Klb = Khb + 64 * KLD;         // 64 x KLD bf16-pairs (lo)
    uint32_t* Vs  = Klb + 64 * KLD;         // 64 x FLD tf32
    uint32_t* Ps  = Vs + 64 * FLD;          // 64 x FLD tf32 (also Q staging)
    float* rawK = (float*)(Ps + 64 * FLD);  // 64 x 64 raw fp32
    float* rawV = rawK + 64 * 64;
    const uint32_t rawK_u = smem_u32(rawK);
    const uint32_t rawV_u = smem_u32(rawV);

    const int tid = threadIdx.x;
    const int wid = tid >> 5;
    const int lane = tid & 31;
    const int gid = lane >> 2;
    const int tig = lane & 3;

    const int h = blockIdx.y;
    const int b = blockIdx.z;
    const int qtile = (TT / 64 - 1) - blockIdx.x;  // heavy CTAs first
    const int qt = qtile * 64;
    const int nkt = qtile + 1;
    const int mrow = wid * 16;

    const float QSC = 0.125f * 1.44269504f;  // 1/sqrt(64) * log2(e)

    const float* Kg = g_K + ((size_t)b * TT) * DMODEL + h * HDIM;
    const float* Vg = g_V + ((size_t)b * TT) * DMODEL + h * HDIM;

    // Kick off tile 0 K/V copy (overlaps Q staging)
#pragma unroll
    for (int i = 0; i < 8; i++) {
        int idx = i * 128 + tid;
        int r = idx >> 4;
        int c4 = (idx & 15) * 4;
        cp16(rawK_u + (r * 64 + c4) * 4, Kg + (size_t)r * DMODEL + c4);
        cp16(rawV_u + (r * 64 + c4) * 4, Vg + (size_t)r * DMODEL + c4);
    }
    cp_commit();

    // Stage scaled Q (fp32) into Ps region, then build bf16 hi/lo fragments
    float* Qstage = (float*)Ps;
    const float* Qg = g_Q + ((size_t)(b * TT + qt)) * DMODEL + h * HDIM;
#pragma unroll
    for (int i = 0; i < 8; i++) {
        int idx = i * 128 + tid;
        int r = idx >> 4;
        int c4 = (idx & 15) * 4;
        float4 v = *(const float4*)(Qg + (size_t)r * DMODEL + c4);
        v.x *= QSC; v.y *= QSC; v.z *= QSC; v.w *= QSC;
        *(float4*)(&Qstage[r * FLD + c4]) = v;
    }
    __syncthreads();

    // Q fragments: 4 k16 slabs, bf16 hi/lo pairs (m16n8k16 A layout)
    uint32_t qah[4][4], qal[4][4];
#pragma unroll
    for (int sl = 0; sl < 4; sl++) {
        const int kb = sl * 16;
#pragma unroll
        for (int fr = 0; fr < 4; fr++) {
            int row = mrow + ((fr & 1) ? 8 : 0) + gid;
            int kp = kb + 2 * tig + ((fr & 2) ? 8 : 0);
            float x0 = Qstage[row * FLD + kp];
            float x1 = Qstage[row * FLD + kp + 1];
            uint32_t hw = pk_bf16(x0, x1);
            qah[sl][fr] = hw;
            qal[sl][fr] = pk_bf16(x0 - bf_lo(hw), x1 - bf_hi(hw));
        }
    }

    float O[8][4];
#pragma unroll
    for (int nt = 0; nt < 8; nt++)
#pragma unroll
        for (int r = 0; r < 4; r++) O[nt][r] = 0.f;
    float m2a = -1e30f, m2b = -1e30f, la = 0.f, lb = 0.f;

    for (int kt = 0; kt < nkt; kt++) {
        cp_wait0();
        __syncthreads();   // raw K/V ready; operand buffers free

        // Convert: K -> bf16 hi/lo pair-packed, V -> tf32
#pragma unroll
        for (int i = 0; i < 8; i++) {
            int idx = i * 128 + tid;
            int r = idx >> 4;
            int c4 = (idx & 15) * 4;
            int c2 = (idx & 15) * 2;
            float4 kv = *(const float4*)(rawK + r * 64 + c4);
            float4 vv = *(const float4*)(rawV + r * 64 + c4);
            uint32_t h01 = pk_bf16(kv.x, kv.y);
            uint32_t h23 = pk_bf16(kv.z, kv.w);
            uint32_t l01 = pk_bf16(kv.x - bf_lo(h01), kv.y - bf_hi(h01));
            uint32_t l23 = pk_bf16(kv.z - bf_lo(h23), kv.w - bf_hi(h23));
            *(uint2*)(&Khb[r * KLD + c2]) = make_uint2(h01, h23);
            *(uint2*)(&Klb[r * KLD + c2]) = make_uint2(l01, l23);
            *(uint4*)(&Vs[r * FLD + c4]) =
                make_uint4(f2tf32(vv.x), f2tf32(vv.y), f2tf32(vv.z), f2tf32(vv.w));
        }
        __syncthreads();   // operands ready; raw free

        // Prefetch next tile (overlaps QK/softmax/PV)
        if (kt + 1 < nkt) {
            const int kn = (kt + 1) * 64;
#pragma unroll
            for (int i = 0; i < 8; i++) {
                int idx = i * 128 + tid;
                int r = idx >> 4;
                int c4 = (idx & 15) * 4;
                cp16(rawK_u + (r * 64 + c4) * 4, Kg + (size_t)(kn + r) * DMODEL + c4);
                cp16(rawV_u + (r * 64 + c4) * 4, Vg + (size_t)(kn + r) * DMODEL + c4);
            }
            cp_commit();
        }

        // --- QK^T: compensated bf16 (3 mmas per k16 slab) ---
        float S[8][4];
#pragma unroll
        for (int nt = 0; nt < 8; nt++)
#pragma unroll
            for (int r = 0; r < 4; r++) S[nt][r] = 0.f;

#pragma unroll
        for (int sl = 0; sl < 4; sl++) {
            const int kw = sl * 8;   // pair-word offset of slab
#pragma unroll
            for (int nt = 0; nt < 8; nt++) {
                const int krow = (nt * 8 + gid) * KLD;
                uint32_t bh[2], bl[2];
                bh[0] = Khb[krow + kw + tig];
                bh[1] = Khb[krow + kw + 4 + tig];
                bl[0] = Klb[krow + kw + tig];
                bl[1] = Klb[krow + kw + 4 + tig];
                MMA_BF16(S[nt], qah[sl], bh);
                MMA_BF16(S[nt], qah[sl], bl);
                MMA_BF16(S[nt], qal[sl], bh);
            }
        }

        // --- causal mask (diagonal tile only) ---
        const int k0 = kt * 64;
        if (kt == nkt - 1) {
            int qa = qt + mrow + gid;
            int qb = qa + 8;
#pragma unroll
            for (int nt = 0; nt < 8; nt++) {
                int kc = k0 + nt * 8 + 2 * tig;
                if (kc > qa)     S[nt][0] = -1e30f;
                if (kc + 1 > qa) S[nt][1] = -1e30f;
                if (kc > qb)     S[nt][2] = -1e30f;
                if (kc + 1 > qb) S[nt][3] = -1e30f;
            }
        }

        // --- online softmax (base 2) ---
        float ma = -1e30f, mb = -1e30f;
#pragma unroll
        for (int nt = 0; nt < 8; nt++) {
            ma = fmaxf(ma, fmaxf(S[nt][0], S[nt][1]));
            mb = fmaxf(mb, fmaxf(S[nt][2], S[nt][3]));
        }
        ma = fmaxf(ma, __shfl_xor_sync(0xFFFFFFFFu, ma, 1));
        ma = fmaxf(ma, __shfl_xor_sync(0xFFFFFFFFu, ma, 2));
        mb = fmaxf(mb, __shfl_xor_sync(0xFFFFFFFFu, mb, 1));
        mb = fmaxf(mb, __shfl_xor_sync(0xFFFFFFFFu, mb, 2));

        float mna = fmaxf(m2a, ma), mnb = fmaxf(m2b, mb);
        float alpa = exp2f(m2a - mna), alpb = exp2f(m2b - mnb);
        m2a = mna; m2b = mnb;
        la *= alpa; lb *= alpb;

        float pa = 0.f, pb = 0.f;
        const int ra = mrow + gid, rb = mrow + 8 + gid;
#pragma unroll
        for (int nt = 0; nt < 8; nt++) {
            float p0 = exp2f(S[nt][0] - mna), p1 = exp2f(S[nt][1] - mna);
            float p2 = exp2f(S[nt][2] - mnb), p3 = exp2f(S[nt][3] - mnb);
            pa += p0 + p1; pb += p2 + p3;
            O[nt][0] *= alpa; O[nt][1] *= alpa;
            O[nt][2] *= alpb; O[nt][3] *= alpb;
            *(uint2*)(&Ps[ra * FLD + nt * 8 + 2 * tig]) =
                make_uint2(f2tf32(p0), f2tf32(p1));
            *(uint2*)(&Ps[rb * FLD + nt * 8 + 2 * tig]) =
                make_uint2(f2tf32(p2), f2tf32(p3));
        }
        pa += __shfl_xor_sync(0xFFFFFFFFu, pa, 1);
        pa += __shfl_xor_sync(0xFFFFFFFFu, pa, 2);
        pb += __shfl_xor_sync(0xFFFFFFFFu, pb, 1);
        pb += __shfl_xor_sync(0xFFFFFFFFu, pb, 2);
        la += pa; lb += pb;

        __syncwarp();

        // --- PV: O += P * V (tf32, unchanged) ---
#pragma unroll
        for (int kk = 0; kk < 8; kk++) {
            const int kw = kk * 8;
            uint32_t av[4];
            av[0] = Ps[ra * FLD + kw + tig];
            av[1] = Ps[rb * FLD + kw + tig];
            av[2] = Ps[ra * FLD + kw + 4 + tig];
            av[3] = Ps[rb * FLD + kw + 4 + tig];
#pragma unroll
            for (int nt = 0; nt < 8; nt++) {
                uint32_t bv[2];
                bv[0] = Vs[(kw + tig) * FLD + nt * 8 + gid];
                bv[1] = Vs[(kw + 4 + tig) * FLD + nt * 8 + gid];
                MMA_TF32(O[nt], av, bv);
            }
        }
    }

    // Epilogue
    const float inva = 1.f / la, invb = 1.f / lb;
    const int ra = qt + mrow + gid, rb = ra + 8;
    float* Oa = g_AO + ((size_t)(b * TT + ra)) * DMODEL + h * HDIM;
    float* Ob = g_AO + ((size_t)(b * TT + rb)) * DMODEL + h * HDIM;
#pragma unroll
    for (int nt = 0; nt < 8; nt++) {
        *(float2*)(Oa + nt * 8 + 2 * tig) =
            make_float2(O[nt][0] * inva, O[nt][1] * inva);
        *(float2*)(Ob + nt * 8 + 2 * tig) =
            make_float2(O[nt][2] * invb, O[nt][3] * invb);
    }
}

// ---------------------------------------------------------------------------
// Launch
// ---------------------------------------------------------------------------
extern "C" void kernel_launch(void* const* d_in, const int* in_sizes, int n_in,
                              void* d_out, int out_size) {
    const float* x  = (const float*)d_in[0];
    const float* Wq = (const float*)d_in[1];
    const float* Wk = (const float*)d_in[2];
    const float* Wv = (const float*)d_in[3];
    const float* Wo = (const float*)d_in[4];
    float* out = (float*)d_out;

    cudaFuncSetAttribute(qkv_kernel, cudaFuncAttributeMaxDynamicSharedMemorySize,
                         (int)GEMM_SMEM);
    cudaFuncSetAttribute(oproj_kernel, cudaFuncAttributeMaxDynamicSharedMemorySize,
                         (int)GEMM_SMEM);
    cudaFuncSetAttribute(flash_mma_kernel, cudaFuncAttributeMaxDynamicSharedMemorySize,
                         (int)FLASH_SMEM);

    dim3 gqkv(DMODEL / 128, (BB * TT) / 128, 3);
    qkv_kernel<<<gqkv, 256, GEMM_SMEM>>>(x, Wq, Wk, Wv);

    dim3 gatt(TT / 64, NHEAD, BB);
    flash_mma_kernel<<<gatt, 128, FLASH_SMEM>>>();

    dim3 gout(DMODEL / 128, (BB * TT) / 128, 1);
    oproj_kernel<<<gout, 256, GEMM_SMEM>>>(Wo, out);
}

// round 16
// speedup vs baseline: 4.6456x; 1.0196x over previous
#include <cuda_runtime.h>
#include <cuda_bf16.h>
#include <cstdint>

// Problem constants
#define BB 2
#define TT 2048
#define DMODEL 1024
#define NHEAD 16
#define HDIM 64

// Scratch (device globals: allocation-free rule)
__device__ float g_Q[(size_t)BB * TT * DMODEL];
__device__ float g_K[(size_t)BB * TT * DMODEL];
__device__ float g_V[(size_t)BB * TT * DMODEL];
__device__ float g_AO[(size_t)BB * TT * DMODEL];

// ---------------------------------------------------------------------------
// Helpers
// ---------------------------------------------------------------------------
__device__ __forceinline__ uint32_t f2tf32(float f) {
    uint32_t u;
    asm("cvt.rna.tf32.f32 %0, %1;" : "=r"(u) : "f"(f));
    return u;
}

__device__ __forceinline__ uint32_t smem_u32(const void* p) {
    uint32_t a;
    asm("{ .reg .u64 t; cvta.to.shared.u64 t, %1; cvt.u32.u64 %0, t; }"
        : "=r"(a) : "l"(p));
    return a;
}

__device__ __forceinline__ void cp16(uint32_t dst, const void* src) {
    asm volatile("cp.async.cg.shared.global [%0], [%1], 16;"
                 :: "r"(dst), "l"(src) : "memory");
}
__device__ __forceinline__ void cp_commit() {
    asm volatile("cp.async.commit_group;" ::: "memory");
}
__device__ __forceinline__ void cp_wait0() {
    asm volatile("cp.async.wait_group 0;" ::: "memory");
}

// pack two floats -> bf16x2 word (x low half, y high half)
__device__ __forceinline__ uint32_t pk_bf16(float x, float y) {
    __nv_bfloat162 h = __float22bfloat162_rn(make_float2(x, y));
    return *reinterpret_cast<uint32_t*>(&h);
}
__device__ __forceinline__ float bf_lo(uint32_t w) {
    __nv_bfloat162 h = *reinterpret_cast<__nv_bfloat162*>(&w);
    return __bfloat162float(h.x);
}
__device__ __forceinline__ float bf_hi(uint32_t w) {
    __nv_bfloat162 h = *reinterpret_cast<__nv_bfloat162*>(&w);
    return __bfloat162float(h.y);
}

#define MMA_TF32(c, a, b)                                                     \
    asm volatile(                                                             \
        "mma.sync.aligned.m16n8k8.row.col.f32.tf32.tf32.f32 "                 \
        "{%0,%1,%2,%3}, {%4,%5,%6,%7}, {%8,%9}, {%0,%1,%2,%3};"               \
        : "+f"((c)[0]), "+f"((c)[1]), "+f"((c)[2]), "+f"((c)[3])              \
        : "r"((a)[0]), "r"((a)[1]), "r"((a)[2]), "r"((a)[3]),                 \
          "r"((b)[0]), "r"((b)[1]))

#define MMA_BF16(c, a, b)                                                     \
    asm volatile(                                                             \
        "mma.sync.aligned.m16n8k16.row.col.f32.bf16.bf16.f32 "                \
        "{%0,%1,%2,%3}, {%4,%5,%6,%7}, {%8,%9}, {%0,%1,%2,%3};"               \
        : "+f"((c)[0]), "+f"((c)[1]), "+f"((c)[2]), "+f"((c)[3])              \
        : "r"((a)[0]), "r"((a)[1]), "r"((a)[2]), "r"((a)[3]),                 \
          "r"((b)[0]), "r"((b)[1]))

// ---------------------------------------------------------------------------
// TF32 mma.sync GEMM (NT): C[M,N] = A[M,K] * W[N,K]^T
// CTA 128x128, 128 threads = 4 warps (2m x 2n), warp tile 64x64, BK=32.
// cp.async raw staging pipeline; fragment dup A:2x B:2x (was 4x/2x).
// ---------------------------------------------------------------------------
#define SLD 36
#define KCHUNKS (DMODEL / 32)
#define GEMM_SMEM ((2 * 128 * SLD + 2 * 128 * 32) * 4)

__device__ __forceinline__ void gemm128_mma(const float* __restrict__ A,
                                            const float* __restrict__ W,
                                            float* __restrict__ C) {
    extern __shared__ uint32_t gsm[];
    uint32_t* sA = gsm;
    uint32_t* sB = sA + 128 * SLD;
    float* rawA = (float*)(sB + 128 * SLD);
    float* rawB = rawA + 128 * 32;
    const uint32_t rawA_u = smem_u32(rawA);
    const uint32_t rawB_u = smem_u32(rawB);

    const int tid = threadIdx.x;
    const int wid = tid >> 5;
    const int lane = tid & 31;
    const int gid = lane >> 2;
    const int tig = lane & 3;
    const int wm = wid >> 1;     // 0..1 : 64 rows each
    const int wn = wid & 1;      // 0..1 : 64 cols each

    const int m0 = blockIdx.y * 128;
    const int n0 = blockIdx.x * 128;

    float acc[4][8][4];
#pragma unroll
    for (int mt = 0; mt < 4; mt++)
#pragma unroll
        for (int nt = 0; nt < 8; nt++)
#pragma unroll
            for (int r = 0; r < 4; r++) acc[mt][nt][r] = 0.f;

    const float* Ap = A + (size_t)m0 * DMODEL;
    const float* Wp = W + (size_t)n0 * DMODEL;

#pragma unroll
    for (int i = 0; i < 8; i++) {
        int idx = i * 128 + tid;
        int r = idx >> 3;
        int c4 = (idx & 7) * 4;
        cp16(rawA_u + (r * 32 + c4) * 4, Ap + (size_t)r * DMODEL + c4);
        cp16(rawB_u + (r * 32 + c4) * 4, Wp + (size_t)r * DMODEL + c4);
    }
    cp_commit();

    for (int kc = 0; kc < KCHUNKS; kc++) {
        cp_wait0();
        __syncthreads();

#pragma unroll
        for (int i = 0; i < 8; i++) {
            int idx = i * 128 + tid;
            int r = idx >> 3;
            int c4 = (idx & 7) * 4;
            float4 av = *(const float4*)(rawA + r * 32 + c4);
            float4 wv = *(const float4*)(rawB + r * 32 + c4);
            *(uint4*)(&sA[r * SLD + c4]) =
                make_uint4(f2tf32(av.x), f2tf32(av.y), f2tf32(av.z), f2tf32(av.w));
            *(uint4*)(&sB[r * SLD + c4]) =
                make_uint4(f2tf32(wv.x), f2tf32(wv.y), f2tf32(wv.z), f2tf32(wv.w));
        }
        __syncthreads();

        if (kc + 1 < KCHUNKS) {
            const int kn = (kc + 1) * 32;
#pragma unroll
            for (int i = 0; i < 8; i++) {
                int idx = i * 128 + tid;
                int r = idx >> 3;
                int c4 = (idx & 7) * 4;
                cp16(rawA_u + (r * 32 + c4) * 4, Ap + (size_t)r * DMODEL + kn + c4);
                cp16(rawB_u + (r * 32 + c4) * 4, Wp + (size_t)r * DMODEL + kn + c4);
            }
            cp_commit();
        }

#pragma unroll
        for (int ks = 0; ks < 4; ks++) {
            const int kk = ks * 8;
            uint32_t af[4][4];
#pragma unroll
            for (int mt = 0; mt < 4; mt++) {
                int m = wm * 64 + mt * 16;
                af[mt][0] = sA[(m + gid) * SLD + kk + tig];
                af[mt][1] = sA[(m + 8 + gid) * SLD + kk + tig];
                af[mt][2] = sA[(m + gid) * SLD + kk + 4 + tig];
                af[mt][3] = sA[(m + 8 + gid) * SLD + kk + 4 + tig];
            }
            uint32_t bf[8][2];
#pragma unroll
            for (int nt = 0; nt < 8; nt++) {
                int n = wn * 64 + nt * 8;
                bf[nt][0] = sB[(n + gid) * SLD + kk + tig];
                bf[nt][1] = sB[(n + gid) * SLD + kk + 4 + tig];
            }
#pragma unroll
            for (int mt = 0; mt < 4; mt++)
#pragma unroll
                for (int nt = 0; nt < 8; nt++)
                    MMA_TF32(acc[mt][nt], af[mt], bf[nt]);
        }
    }

#pragma unroll
    for (int mt = 0; mt < 4; mt++) {
        int mbase = m0 + wm * 64 + mt * 16;
#pragma unroll
        for (int nt = 0; nt < 8; nt++) {
            int nbase = n0 + wn * 64 + nt * 8 + 2 * tig;
            float* C0 = C + (size_t)(mbase + gid) * DMODEL + nbase;
            float* C1 = C + (size_t)(mbase + 8 + gid) * DMODEL + nbase;
            *(float2*)C0 = make_float2(acc[mt][nt][0], acc[mt][nt][1]);
            *(float2*)C1 = make_float2(acc[mt][nt][2], acc[mt][nt][3]);
        }
    }
}

__global__ __launch_bounds__(128) void qkv_kernel(const float* __restrict__ x,
                                                  const float* __restrict__ Wq,
                                                  const float* __restrict__ Wk,
                                                  const float* __restrict__ Wv) {
    const float* W;
    float* C;
    if (blockIdx.z == 0)      { W = Wq; C = g_Q; }
    else if (blockIdx.z == 1) { W = Wk; C = g_K; }
    else                      { W = Wv; C = g_V; }
    gemm128_mma(x, W, C);
}

__global__ __launch_bounds__(128) void oproj_kernel(const float* __restrict__ Wo,
                                                    float* __restrict__ out) {
    gemm128_mma(g_AO, Wo, out);
}

// ---------------------------------------------------------------------------
// Flash attention (causal): 128 q-rows/CTA, 8 warps x 16 rows, 64-key tiles.
// QK^T = compensated bf16 (Q smem-resident hi/lo), PV = tf32. Direct LDG
// staging (cp.async proven neutral). 2 CTAs/SM -> 16 warps/SM.
// ---------------------------------------------------------------------------
#define FLD 68   // tf32/fp32 row stride (words)
#define KLD 36   // bf16-pair row stride (words)
#define FLASH_SMEM ((2 * 128 * KLD + 2 * 64 * KLD + 64 * FLD + 128 * FLD) * 4)

__global__ __launch_bounds__(256, 2) void flash_mma_kernel() {
    extern __shared__ uint32_t dsm[];
    uint32_t* Qhb = dsm;                    // 128 x KLD bf16-pairs (hi)
    uint32_t* Qlb = Qhb + 128 * KLD;        // 128 x KLD (lo)
    uint32_t* Khb = Qlb + 128 * KLD;        // 64 x KLD (hi)
    uint32_t* Klb = Khb + 64 * KLD;         // 64 x KLD (lo)
    uint32_t* Vs  = Klb + 64 * KLD;         // 64 x FLD tf32
    uint32_t* Ps  = Vs + 64 * FLD;          // 128 x FLD tf32 (also Q staging)

    const int tid = threadIdx.x;
    const int wid = tid >> 5;
    const int lane = tid & 31;
    const int gid = lane >> 2;
    const int tig = lane & 3;

    const int h = blockIdx.y;
    const int b = blockIdx.z;
    const int qtile = (TT / 128 - 1) - blockIdx.x;  // heavy CTAs first
    const int qt = qtile * 128;
    const int nkt = qt / 64 + 2;
    const int mrow = wid * 16;

    const float QSC = 0.125f * 1.44269504f;  // 1/sqrt(64) * log2(e)

    const float* Kg = g_K + ((size_t)b * TT) * DMODEL + h * HDIM;
    const float* Vg = g_V + ((size_t)b * TT) * DMODEL + h * HDIM;

    // Stage scaled Q (fp32) into Ps region
    float* Qstage = (float*)Ps;
    const float* Qg = g_Q + ((size_t)(b * TT + qt)) * DMODEL + h * HDIM;
#pragma unroll
    for (int i = 0; i < 8; i++) {
        int idx = i * 256 + tid;
        int r = idx >> 4;             // 0..127
        int c4 = (idx & 15) * 4;
        float4 v = *(const float4*)(Qg + (size_t)r * DMODEL + c4);
        v.x *= QSC; v.y *= QSC; v.z *= QSC; v.w *= QSC;
        *(float4*)(&Qstage[r * FLD + c4]) = v;
    }
    __syncthreads();

    // Convert Q to bf16 hi/lo pair-packed
#pragma unroll
    for (int i = 0; i < 16; i++) {
        int idx = i * 256 + tid;
        int r = idx >> 5;             // 0..127
        int c2 = idx & 31;            // pair index 0..31
        float2 x = *(const float2*)(&Qstage[r * FLD + 2 * c2]);
        uint32_t hw = pk_bf16(x.x, x.y);
        Qhb[r * KLD + c2] = hw;
        Qlb[r * KLD + c2] = pk_bf16(x.x - bf_lo(hw), x.y - bf_hi(hw));
    }

    float O[8][4];
#pragma unroll
    for (int nt = 0; nt < 8; nt++)
#pragma unroll
        for (int r = 0; r < 4; r++) O[nt][r] = 0.f;
    float m2a = -1e30f, m2b = -1e30f, la = 0.f, lb = 0.f;

    for (int kt = 0; kt < nkt; kt++) {
        const int k0 = kt * 64;
        __syncthreads();   // prev tile's K/V/P reads complete (and Q convert on kt=0)

        // Load + convert K (bf16 hi/lo) and V (tf32)
#pragma unroll
        for (int i = 0; i < 4; i++) {
            int idx = i * 256 + tid;
            int r = idx >> 4;         // 0..63
            int c4 = (idx & 15) * 4;
            int c2 = (idx & 15) * 2;
            float4 kv = *(const float4*)(Kg + (size_t)(k0 + r) * DMODEL + c4);
            float4 vv = *(const float4*)(Vg + (size_t)(k0 + r) * DMODEL + c4);
            uint32_t h01 = pk_bf16(kv.x, kv.y);
            uint32_t h23 = pk_bf16(kv.z, kv.w);
            uint32_t l01 = pk_bf16(kv.x - bf_lo(h01), kv.y - bf_hi(h01));
            uint32_t l23 = pk_bf16(kv.z - bf_lo(h23), kv.w - bf_hi(h23));
            *(uint2*)(&Khb[r * KLD + c2]) = make_uint2(h01, h23);
            *(uint2*)(&Klb[r * KLD + c2]) = make_uint2(l01, l23);
            *(uint4*)(&Vs[r * FLD + c4]) =
                make_uint4(f2tf32(vv.x), f2tf32(vv.y), f2tf32(vv.z), f2tf32(vv.w));
        }
        __syncthreads();

        // --- QK^T: compensated bf16 (3 mmas per k16 slab) ---
        float S[8][4];
#pragma unroll
        for (int nt = 0; nt < 8; nt++)
#pragma unroll
            for (int r = 0; r < 4; r++) S[nt][r] = 0.f;

#pragma unroll
        for (int sl = 0; sl < 4; sl++) {
            const int kw = sl * 8;
            uint32_t qah[4], qal[4];
            qah[0] = Qhb[(mrow + gid) * KLD + kw + tig];
            qah[1] = Qhb[(mrow + 8 + gid) * KLD + kw + tig];
            qah[2] = Qhb[(mrow + gid) * KLD + kw + 4 + tig];
            qah[3] = Qhb[(mrow + 8 + gid) * KLD + kw + 4 + tig];
            qal[0] = Qlb[(mrow + gid) * KLD + kw + tig];
            qal[1] = Qlb[(mrow + 8 + gid) * KLD + kw + tig];
            qal[2] = Qlb[(mrow + gid) * KLD + kw + 4 + tig];
            qal[3] = Qlb[(mrow + 8 + gid) * KLD + kw + 4 + tig];
#pragma unroll
            for (int nt = 0; nt < 8; nt++) {
                const int krow = (nt * 8 + gid) * KLD;
                uint32_t bh[2], bl[2];
                bh[0] = Khb[krow + kw + tig];
                bh[1] = Khb[krow + kw + 4 + tig];
                bl[0] = Klb[krow + kw + tig];
                bl[1] = Klb[krow + kw + 4 + tig];
                MMA_BF16(S[nt], qah, bh);
                MMA_BF16(S[nt], qah, bl);
                MMA_BF16(S[nt], qal, bh);
            }
        }

        // --- causal mask (warp-level condition handles diagonal + future) ---
        if (k0 + 63 > qt + mrow) {
            int qa = qt + mrow + gid;
            int qb = qa + 8;
#pragma unroll
            for (int nt = 0; nt < 8; nt++) {
                int kc = k0 + nt * 8 + 2 * tig;
                if (kc > qa)     S[nt][0] = -1e30f;
                if (kc + 1 > qa) S[nt][1] = -1e30f;
                if (kc > qb)     S[nt][2] = -1e30f;
                if (kc + 1 > qb) S[nt][3] = -1e30f;
            }
        }

        // --- online softmax (base 2) ---
        float ma = -1e30f, mb = -1e30f;
#pragma unroll
        for (int nt = 0; nt < 8; nt++) {
            ma = fmaxf(ma, fmaxf(S[nt][0], S[nt][1]));
            mb = fmaxf(mb, fmaxf(S[nt][2], S[nt][3]));
        }
        ma = fmaxf(ma, __shfl_xor_sync(0xFFFFFFFFu, ma, 1));
        ma = fmaxf(ma, __shfl_xor_sync(0xFFFFFFFFu, ma, 2));
        mb = fmaxf(mb, __shfl_xor_sync(0xFFFFFFFFu, mb, 1));
        mb = fmaxf(mb, __shfl_xor_sync(0xFFFFFFFFu, mb, 2));

        float mna = fmaxf(m2a, ma), mnb = fmaxf(m2b, mb);
        float alpa = exp2f(m2a - mna), alpb = exp2f(m2b - mnb);
        m2a = mna; m2b = mnb;
        la *= alpa; lb *= alpb;

        float pa = 0.f, pb = 0.f;
        const int ra = mrow + gid, rb = mrow + 8 + gid;
#pragma unroll
        for (int nt = 0; nt < 8; nt++) {
            float p0 = exp2f(S[nt][0] - mna), p1 = exp2f(S[nt][1] - mna);
            float p2 = exp2f(S[nt][2] - mnb), p3 = exp2f(S[nt][3] - mnb);
            pa += p0 + p1; pb += p2 + p3;
            O[nt][0] *= alpa; O[nt][1] *= alpa;
            O[nt][2] *= alpb; O[nt][3] *= alpb;
            *(uint2*)(&Ps[ra * FLD + nt * 8 + 2 * tig]) =
                make_uint2(f2tf32(p0), f2tf32(p1));
            *(uint2*)(&Ps[rb * FLD + nt * 8 + 2 * tig]) =
                make_uint2(f2tf32(p2), f2tf32(p3));
        }
        pa += __shfl_xor_sync(0xFFFFFFFFu, pa, 1);
        pa += __shfl_xor_sync(0xFFFFFFFFu, pa, 2);
        pb += __shfl_xor_sync(0xFFFFFFFFu, pb, 1);
        pb += __shfl_xor_sync(0xFFFFFFFFu, pb, 2);
        la += pa; lb += pb;

        __syncwarp();   // P rows are warp-private: warp-local sync suffices

        // --- PV: O += P * V (tf32) ---
#pragma unroll
        for (int kk = 0; kk < 8; kk++) {
            const int kw = kk * 8;
            uint32_t av[4];
            av[0] = Ps[ra * FLD + kw + tig];
            av[1] = Ps[rb * FLD + kw + tig];
            av[2] = Ps[ra * FLD + kw + 4 + tig];
            av[3] = Ps[rb * FLD + kw + 4 + tig];
#pragma unroll
            for (int nt = 0; nt < 8; nt++) {
                uint32_t bv[2];
                bv[0] = Vs[(kw + tig) * FLD + nt * 8 + gid];
                bv[1] = Vs[(kw + 4 + tig) * FLD + nt * 8 + gid];
                MMA_TF32(O[nt], av, bv);
            }
        }
    }

    // Epilogue
    const float inva = 1.f / la, invb = 1.f / lb;
    const int ra = qt + mrow + gid, rb = ra + 8;
    float* Oa = g_AO + ((size_t)(b * TT + ra)) * DMODEL + h * HDIM;
    float* Ob = g_AO + ((size_t)(b * TT + rb)) * DMODEL + h * HDIM;
#pragma unroll
    for (int nt = 0; nt < 8; nt++) {
        *(float2*)(Oa + nt * 8 + 2 * tig) =
            make_float2(O[nt][0] * inva, O[nt][1] * inva);
        *(float2*)(Ob + nt * 8 + 2 * tig) =
            make_float2(O[nt][2] * invb, O[nt][3] * invb);
    }
}

// ---------------------------------------------------------------------------
// Launch
// ---------------------------------------------------------------------------
extern "C" void kernel_launch(void* const* d_in, const int* in_sizes, int n_in,
                              void* d_out, int out_size) {
    const float* x  = (const float*)d_in[0];
    const float* Wq = (const float*)d_in[1];
    const float* Wk = (const float*)d_in[2];
    const float* Wv = (const float*)d_in[3];
    const float* Wo = (const float*)d_in[4];
    float* out = (float*)d_out;

    cudaFuncSetAttribute(qkv_kernel, cudaFuncAttributeMaxDynamicSharedMemorySize,
                         (int)GEMM_SMEM);
    cudaFuncSetAttribute(oproj_kernel, cudaFuncAttributeMaxDynamicSharedMemorySize,
                         (int)GEMM_SMEM);
    cudaFuncSetAttribute(flash_mma_kernel, cudaFuncAttributeMaxDynamicSharedMemorySize,
                         (int)FLASH_SMEM);

    dim3 gqkv(DMODEL / 128, (BB * TT) / 128, 3);
    qkv_kernel<<<gqkv, 128, GEMM_SMEM>>>(x, Wq, Wk, Wv);

    dim3 gatt(TT / 128, NHEAD, BB);
    flash_mma_kernel<<<gatt, 256, FLASH_SMEM>>>();

    dim3 gout(DMODEL / 128, (BB * TT) / 128, 1);
    oproj_kernel<<<gout, 128, GEMM_SMEM>>>(Wo, out);
}

// round 17
// speedup vs baseline: 5.8695x; 1.2635x over previous
#include <cuda_runtime.h>
#include <cuda_bf16.h>
#include <cuda_fp16.h>
#include <cstdint>

// Problem constants
#define BB 2
#define TT 2048
#define DMODEL 1024
#define NHEAD 16
#define HDIM 64

// Scratch (device globals: allocation-free rule)
__device__ float g_Q[(size_t)BB * TT * DMODEL];
__device__ float g_K[(size_t)BB * TT * DMODEL];
__device__ float g_V[(size_t)BB * TT * DMODEL];
__device__ float g_AO[(size_t)BB * TT * DMODEL];

// ---------------------------------------------------------------------------
// Helpers
// ---------------------------------------------------------------------------
__device__ __forceinline__ uint32_t pk_f16(float x, float y) {
    __half2 h = __float22half2_rn(make_float2(x, y));
    return *reinterpret_cast<uint32_t*>(&h);
}

#define MMA_F16(c, a, b)                                                      \
    asm volatile(                                                             \
        "mma.sync.aligned.m16n8k16.row.col.f32.f16.f16.f32 "                  \
        "{%0,%1,%2,%3}, {%4,%5,%6,%7}, {%8,%9}, {%0,%1,%2,%3};"               \
        : "+f"((c)[0]), "+f"((c)[1]), "+f"((c)[2]), "+f"((c)[3])              \
        : "r"((a)[0]), "r"((a)[1]), "r"((a)[2]), "r"((a)[3]),                 \
          "r"((b)[0]), "r"((b)[1]))

// ---------------------------------------------------------------------------
// FP16 mma.sync GEMM (NT): C[M,N] = A[M,K] * W[N,K]^T
// CTA 128x128, 128 threads = 4 warps (2m x 2n), warp tile 64x64, chunk K=64.
// Operands stored as fp16 pair-packed words, row stride 36 (conflict-free).
// ---------------------------------------------------------------------------
#define SLD2 36
#define GCHUNKS (DMODEL / 64)
#define GEMM_SMEM (2 * 128 * SLD2 * 4)

__device__ __forceinline__ void gemm128_f16(const float* __restrict__ A,
                                            const float* __restrict__ W,
                                            float* __restrict__ C) {
    extern __shared__ uint32_t gsm[];
    uint32_t* sA = gsm;                 // 128 rows x 32 pairs (+4 pad)
    uint32_t* sB = sA + 128 * SLD2;

    const int tid = threadIdx.x;
    const int wid = tid >> 5;
    const int lane = tid & 31;
    const int gid = lane >> 2;
    const int tig = lane & 3;
    const int wm = wid >> 1;            // 0..1 : 64 rows
    const int wn = wid & 1;             // 0..1 : 64 cols

    const int m0 = blockIdx.y * 128;
    const int n0 = blockIdx.x * 128;

    float acc[4][8][4];
#pragma unroll
    for (int mt = 0; mt < 4; mt++)
#pragma unroll
        for (int nt = 0; nt < 8; nt++)
#pragma unroll
            for (int r = 0; r < 4; r++) acc[mt][nt][r] = 0.f;

    const float* Ap = A + (size_t)m0 * DMODEL;
    const float* Wp = W + (size_t)n0 * DMODEL;

    for (int kc = 0; kc < GCHUNKS; kc++) {
        const int k0 = kc * 64;
        __syncthreads();
        // Load + pack fp16 pairs. 128 rows x 16 float4 per matrix.
#pragma unroll
        for (int i = 0; i < 16; i++) {
            int idx = i * 128 + tid;
            int r = idx >> 4;
            int cq = idx & 15;
            float4 av = *(const float4*)(Ap + (size_t)r * DMODEL + k0 + cq * 4);
            float4 wv = *(const float4*)(Wp + (size_t)r * DMODEL + k0 + cq * 4);
            *(uint2*)(&sA[r * SLD2 + cq * 2]) =
                make_uint2(pk_f16(av.x, av.y), pk_f16(av.z, av.w));
            *(uint2*)(&sB[r * SLD2 + cq * 2]) =
                make_uint2(pk_f16(wv.x, wv.y), pk_f16(wv.z, wv.w));
        }
        __syncthreads();

#pragma unroll
        for (int sl = 0; sl < 4; sl++) {
            const int kp = sl * 8;
            uint32_t af[4][4];
#pragma unroll
            for (int mt = 0; mt < 4; mt++) {
                int m = wm * 64 + mt * 16;
                af[mt][0] = sA[(m + gid) * SLD2 + kp + tig];
                af[mt][1] = sA[(m + 8 + gid) * SLD2 + kp + tig];
                af[mt][2] = sA[(m + gid) * SLD2 + kp + 4 + tig];
                af[mt][3] = sA[(m + 8 + gid) * SLD2 + kp + 4 + tig];
            }
            uint32_t bfr[8][2];
#pragma unroll
            for (int nt = 0; nt < 8; nt++) {
                int n = wn * 64 + nt * 8;
                bfr[nt][0] = sB[(n + gid) * SLD2 + kp + tig];
                bfr[nt][1] = sB[(n + gid) * SLD2 + kp + 4 + tig];
            }
#pragma unroll
            for (int mt = 0; mt < 4; mt++)
#pragma unroll
                for (int nt = 0; nt < 8; nt++)
                    MMA_F16(acc[mt][nt], af[mt], bfr[nt]);
        }
    }

#pragma unroll
    for (int mt = 0; mt < 4; mt++) {
        int mbase = m0 + wm * 64 + mt * 16;
#pragma unroll
        for (int nt = 0; nt < 8; nt++) {
            int nbase = n0 + wn * 64 + nt * 8 + 2 * tig;
            float* C0 = C + (size_t)(mbase + gid) * DMODEL + nbase;
            float* C1 = C + (size_t)(mbase + 8 + gid) * DMODEL + nbase;
            *(float2*)C0 = make_float2(acc[mt][nt][0], acc[mt][nt][1]);
            *(float2*)C1 = make_float2(acc[mt][nt][2], acc[mt][nt][3]);
        }
    }
}

__global__ __launch_bounds__(128) void qkv_kernel(const float* __restrict__ x,
                                                  const float* __restrict__ Wq,
                                                  const float* __restrict__ Wk,
                                                  const float* __restrict__ Wv) {
    const float* W;
    float* C;
    if (blockIdx.z == 0)      { W = Wq; C = g_Q; }
    else if (blockIdx.z == 1) { W = Wk; C = g_K; }
    else                      { W = Wv; C = g_V; }
    gemm128_f16(x, W, C);
}

__global__ __launch_bounds__(128) void oproj_kernel(const float* __restrict__ Wo,
                                                    float* __restrict__ out) {
    gemm128_f16(g_AO, Wo, out);
}

// ---------------------------------------------------------------------------
// Flash attention (causal), all-fp16 MMA:
//   QK^T: plain fp16 m16n8k16 (1 mma per slab), Q/K pair-packed in smem.
//   PV:   fp16 m16n8k16, P passed in REGISTERS (C-frag == A-frag layout),
//         V stored key-pair-packed (transposed halves, stride 37 words).
// 128 q-rows/CTA, 8 warps x 16 rows, 64-key tiles, 2 CTAs/SM.
// ---------------------------------------------------------------------------
#define QLD 36             // Q/K pair-word row stride
#define VLDW 37            // V word stride per dim-row (74 halves)
#define FLASH_SMEM ((128 * QLD + 64 * QLD + 64 * VLDW) * 4)

__global__ __launch_bounds__(256, 2) void flash_mma_kernel() {
    extern __shared__ uint32_t dsm[];
    uint32_t* QhF = dsm;                       // 128 x QLD fp16-pairs
    uint32_t* KhF = QhF + 128 * QLD;           // 64 x QLD fp16-pairs
    uint32_t* VsF = KhF + 64 * QLD;            // 64 dims x VLDW words (key pairs)
    __half*   VsH = (__half*)VsF;

    const int tid = threadIdx.x;
    const int wid = tid >> 5;
    const int lane = tid & 31;
    const int gid = lane >> 2;
    const int tig = lane & 3;

    const int h = blockIdx.y;
    const int b = blockIdx.z;
    const int qtile = (TT / 128 - 1) - blockIdx.x;  // heavy CTAs first
    const int qt = qtile * 128;
    const int nkt = qt / 64 + 2;
    const int mrow = wid * 16;

    const float QSC = 0.125f * 1.44269504f;  // 1/sqrt(64) * log2(e)

    const float* Kg = g_K + ((size_t)b * TT) * DMODEL + h * HDIM;
    const float* Vg = g_V + ((size_t)b * TT) * DMODEL + h * HDIM;

    // Stage Q directly as scaled fp16 pairs (no fp32 staging buffer)
    const float* Qg = g_Q + ((size_t)(b * TT + qt)) * DMODEL + h * HDIM;
#pragma unroll
    for (int i = 0; i < 8; i++) {
        int idx = i * 256 + tid;
        int r = idx >> 4;               // 0..127
        int cq = idx & 15;              // float4 col
        float4 v = *(const float4*)(Qg + (size_t)r * DMODEL + cq * 4);
        v.x *= QSC; v.y *= QSC; v.z *= QSC; v.w *= QSC;
        *(uint2*)(&QhF[r * QLD + cq * 2]) =
            make_uint2(pk_f16(v.x, v.y), pk_f16(v.z, v.w));
    }

    float O[8][4];
#pragma unroll
    for (int nt = 0; nt < 8; nt++)
#pragma unroll
        for (int r = 0; r < 4; r++) O[nt][r] = 0.f;
    float m2a = -1e30f, m2b = -1e30f, la = 0.f, lb = 0.f;

    for (int kt = 0; kt < nkt; kt++) {
        const int k0 = kt * 64;
        __syncthreads();   // prev tile reads done (and Q staging on kt=0)

        // K -> fp16 pairs (row-major); V -> transposed half layout:
        // VsH[dim * 2*VLDW + key]
#pragma unroll
        for (int i = 0; i < 4; i++) {
            int idx = i * 256 + tid;
            int r = idx >> 4;           // key 0..63
            int cq = idx & 15;
            float4 kv = *(const float4*)(Kg + (size_t)(k0 + r) * DMODEL + cq * 4);
            float4 vv = *(const float4*)(Vg + (size_t)(k0 + r) * DMODEL + cq * 4);
            *(uint2*)(&KhF[r * QLD + cq * 2]) =
                make_uint2(pk_f16(kv.x, kv.y), pk_f16(kv.z, kv.w));
            int c0 = cq * 4;
            VsH[(c0 + 0) * (2 * VLDW) + r] = __float2half_rn(vv.x);
            VsH[(c0 + 1) * (2 * VLDW) + r] = __float2half_rn(vv.y);
            VsH[(c0 + 2) * (2 * VLDW) + r] = __float2half_rn(vv.z);
            VsH[(c0 + 3) * (2 * VLDW) + r] = __float2half_rn(vv.w);
        }
        __syncthreads();

        // --- QK^T: plain fp16, 1 mma per (slab, nt) ---
        float S[8][4];
#pragma unroll
        for (int nt = 0; nt < 8; nt++)
#pragma unroll
            for (int r = 0; r < 4; r++) S[nt][r] = 0.f;

#pragma unroll
        for (int sl = 0; sl < 4; sl++) {
            const int kp = sl * 8;
            uint32_t qa[4];
            qa[0] = QhF[(mrow + gid) * QLD + kp + tig];
            qa[1] = QhF[(mrow + 8 + gid) * QLD + kp + tig];
            qa[2] = QhF[(mrow + gid) * QLD + kp + 4 + tig];
            qa[3] = QhF[(mrow + 8 + gid) * QLD + kp + 4 + tig];
#pragma unroll
            for (int nt = 0; nt < 8; nt++) {
                uint32_t bh[2];
                bh[0] = KhF[(nt * 8 + gid) * QLD + kp + tig];
                bh[1] = KhF[(nt * 8 + gid) * QLD + kp + 4 + tig];
                MMA_F16(S[nt], qa, bh);
            }
        }

        // --- causal mask ---
        if (k0 + 63 > qt + mrow) {
            int qa_ = qt + mrow + gid;
            int qb_ = qa_ + 8;
#pragma unroll
            for (int nt = 0; nt < 8; nt++) {
                int kc = k0 + nt * 8 + 2 * tig;
                if (kc > qa_)     S[nt][0] = -1e30f;
                if (kc + 1 > qa_) S[nt][1] = -1e30f;
                if (kc > qb_)     S[nt][2] = -1e30f;
                if (kc + 1 > qb_) S[nt][3] = -1e30f;
            }
        }

        // --- online softmax (base 2); p left in S registers ---
        float ma = -1e30f, mb = -1e30f;
#pragma unroll
        for (int nt = 0; nt < 8; nt++) {
            ma = fmaxf(ma, fmaxf(S[nt][0], S[nt][1]));
            mb = fmaxf(mb, fmaxf(S[nt][2], S[nt][3]));
        }
        ma = fmaxf(ma, __shfl_xor_sync(0xFFFFFFFFu, ma, 1));
        ma = fmaxf(ma, __shfl_xor_sync(0xFFFFFFFFu, ma, 2));
        mb = fmaxf(mb, __shfl_xor_sync(0xFFFFFFFFu, mb, 1));
        mb = fmaxf(mb, __shfl_xor_sync(0xFFFFFFFFu, mb, 2));

        float mna = fmaxf(m2a, ma), mnb = fmaxf(m2b, mb);
        float alpa = exp2f(m2a - mna), alpb = exp2f(m2b - mnb);
        m2a = mna; m2b = mnb;
        la *= alpa; lb *= alpb;

        float pa = 0.f, pb = 0.f;
#pragma unroll
        for (int nt = 0; nt < 8; nt++) {
            S[nt][0] = exp2f(S[nt][0] - mna);
            S[nt][1] = exp2f(S[nt][1] - mna);
            S[nt][2] = exp2f(S[nt][2] - mnb);
            S[nt][3] = exp2f(S[nt][3] - mnb);
            pa += S[nt][0] + S[nt][1];
            pb += S[nt][2] + S[nt][3];
            O[nt][0] *= alpa; O[nt][1] *= alpa;
            O[nt][2] *= alpb; O[nt][3] *= alpb;
        }
        pa += __shfl_xor_sync(0xFFFFFFFFu, pa, 1);
        pa += __shfl_xor_sync(0xFFFFFFFFu, pa, 2);
        pb += __shfl_xor_sync(0xFFFFFFFFu, pb, 1);
        pb += __shfl_xor_sync(0xFFFFFFFFu, pb, 2);
        la += pa; lb += pb;

        // --- PV: O += P * V; P packed from registers (C-frag == A-frag) ---
#pragma unroll
        for (int sl = 0; sl < 4; sl++) {
            uint32_t av[4];
            av[0] = pk_f16(S[2 * sl][0], S[2 * sl][1]);
            av[1] = pk_f16(S[2 * sl][2], S[2 * sl][3]);
            av[2] = pk_f16(S[2 * sl + 1][0], S[2 * sl + 1][1]);
            av[3] = pk_f16(S[2 * sl + 1][2], S[2 * sl + 1][3]);
#pragma unroll
            for (int nt = 0; nt < 8; nt++) {
                uint32_t bv[2];
                bv[0] = VsF[(nt * 8 + gid) * VLDW + sl * 8 + tig];
                bv[1] = VsF[(nt * 8 + gid) * VLDW + sl * 8 + 4 + tig];
                MMA_F16(O[nt], av, bv);
            }
        }
    }

    // Epilogue
    const float inva = 1.f / la, invb = 1.f / lb;
    const int ra = qt + mrow + gid, rb = ra + 8;
    float* Oa = g_AO + ((size_t)(b * TT + ra)) * DMODEL + h * HDIM;
    float* Ob = g_AO + ((size_t)(b * TT + rb)) * DMODEL + h * HDIM;
#pragma unroll
    for (int nt = 0; nt < 8; nt++) {
        *(float2*)(Oa + nt * 8 + 2 * tig) =
            make_float2(O[nt][0] * inva, O[nt][1] * inva);
        *(float2*)(Ob + nt * 8 + 2 * tig) =
            make_float2(O[nt][2] * invb, O[nt][3] * invb);
    }
}

// ---------------------------------------------------------------------------
// Launch
// ---------------------------------------------------------------------------
extern "C" void kernel_launch(void* const* d_in, const int* in_sizes, int n_in,
                              void* d_out, int out_size) {
    const float* x  = (const float*)d_in[0];
    const float* Wq = (const float*)d_in[1];
    const float* Wk = (const float*)d_in[2];
    const float* Wv = (const float*)d_in[3];
    const float* Wo = (const float*)d_in[4];
    float* out = (float*)d_out;

    cudaFuncSetAttribute(qkv_kernel, cudaFuncAttributeMaxDynamicSharedMemorySize,
                         (int)GEMM_SMEM);
    cudaFuncSetAttribute(oproj_kernel, cudaFuncAttributeMaxDynamicSharedMemorySize,
                         (int)GEMM_SMEM);
    cudaFuncSetAttribute(flash_mma_kernel, cudaFuncAttributeMaxDynamicSharedMemorySize,
                         (int)FLASH_SMEM);

    dim3 gqkv(DMODEL / 128, (BB * TT) / 128, 3);
    qkv_kernel<<<gqkv, 128, GEMM_SMEM>>>(x, Wq, Wk, Wv);

    dim3 gatt(TT / 128, NHEAD, BB);
    flash_mma_kernel<<<gatt, 256, FLASH_SMEM>>>();

    dim3 gout(DMODEL / 128, (BB * TT) / 128, 1);
    oproj_kernel<<<gout, 128, GEMM_SMEM>>>(Wo, out);
}